// round 1
// baseline (speedup 1.0000x reference)
#include <cuda_runtime.h>
#include <math.h>

#define TT   2048      // tokens (B*S)
#define DD   1024      // model dim
#define EE   16        // experts
#define HH   1024      // expert hidden
#define KK   4         // top-k
#define TKS  (TT*KK)   // total (token,expert) slots = 8192
#define EPSF 1e-6f

// ---------------- device scratch (statically allocated; no cudaMalloc) ------
__device__ float g_ssum[EE];            // sum of normalized scores per expert
__device__ int   g_counts[EE];
__device__ int   g_offsets[EE];
__device__ int   g_fill[EE];
__device__ int   g_tok[TKS];            // token id per slot (grouped by expert)
__device__ float g_wt[TKS];             // combine weight per slot
__device__ int   g_topk_e[TKS];         // per-token top-k expert ids
__device__ float g_topk_w[TKS];         // per-token top-k weights
__device__ float g_hbuf[(size_t)TKS * HH];   // x @ w1  per slot
__device__ float g_gbuf[(size_t)TKS * HH];   // x @ w3  per slot

// ---------------- 0: zero output + counters ---------------------------------
__global__ void zero_kernel(float* __restrict__ out, int out_size) {
    int i = blockIdx.x * blockDim.x + threadIdx.x;
    if (i < out_size) out[i] = 0.0f;
    if (i < EE) { g_counts[i] = 0; g_ssum[i] = 0.0f; g_fill[i] = 0; }
}

// ---------------- 1: router --------------------------------------------------
// one block per token, 128 threads
__global__ void router_kernel(const float* __restrict__ x,
                              const float* __restrict__ gw,
                              const float* __restrict__ bias) {
    int t = blockIdx.x;
    __shared__ float xs[DD];
    __shared__ float logits[EE];
    __shared__ float scores[EE];
    int tid = threadIdx.x;
    for (int d = tid; d < DD; d += 128) xs[d] = x[t * DD + d];
    __syncthreads();

    int warp = tid >> 5, lane = tid & 31;
    for (int e = warp; e < EE; e += 4) {
        float s = 0.0f;
        for (int d = lane; d < DD; d += 32) s += xs[d] * gw[d * EE + e];
        #pragma unroll
        for (int o = 16; o; o >>= 1) s += __shfl_down_sync(0xffffffff, s, o);
        if (lane == 0) logits[e] = s + bias[e];
    }
    __syncthreads();

    if (tid == 0) {
        float ssum = 0.0f;
        #pragma unroll
        for (int e = 0; e < EE; e++) {
            float sc = 1.0f / (1.0f + expf(-logits[e]));
            scores[e] = sc; ssum += sc;
        }
        float inv = 1.0f / (ssum + EPSF);
        #pragma unroll
        for (int e = 0; e < EE; e++) {
            scores[e] *= inv;
            atomicAdd(&g_ssum[e], scores[e]);   // for avg_prob
        }
        // top-4 selection (first occurrence wins ties, like lax.top_k)
        unsigned used = 0u;
        int   idx[KK];
        float val[KK];
        float wsum = 0.0f;
        #pragma unroll
        for (int k = 0; k < KK; k++) {
            float best = -1e30f; int bi = 0;
            #pragma unroll
            for (int e = 0; e < EE; e++) {
                if (!((used >> e) & 1u) && scores[e] > best) { best = scores[e]; bi = e; }
            }
            used |= (1u << bi);
            idx[k] = bi; val[k] = best; wsum += best;
        }
        float winv = 1.0f / (wsum + EPSF);
        #pragma unroll
        for (int k = 0; k < KK; k++) {
            g_topk_e[t * KK + k] = idx[k];
            g_topk_w[t * KK + k] = val[k] * winv;
            atomicAdd(&g_counts[idx[k]], 1);
        }
    }
}

// ---------------- 2: scan + lb loss ------------------------------------------
__global__ void scan_kernel(float* __restrict__ out, int out_size) {
    if (threadIdx.x == 0 && blockIdx.x == 0) {
        int off = 0;
        #pragma unroll
        for (int e = 0; e < EE; e++) { g_offsets[e] = off; off += g_counts[e]; }
        float lb = 0.0f;
        #pragma unroll
        for (int e = 0; e < EE; e++)
            lb += (float)g_counts[e] * g_ssum[e];
        lb *= (float)EE / ((float)TT * (float)TT);
        if (out_size > TT * DD) out[TT * DD] = lb;
    }
}

// ---------------- 3: scatter tokens into expert-grouped lists ----------------
__global__ void scatter_kernel() {
    int i = blockIdx.x * blockDim.x + threadIdx.x;
    if (i >= TKS) return;
    int t = i >> 2;
    int e = g_topk_e[i];
    int pos = atomicAdd(&g_fill[e], 1);
    int slot = g_offsets[e] + pos;
    g_tok[slot] = t;
    g_wt[slot]  = g_topk_w[i];
}

// ---------------- 4/5: GEMM1  dst[slot,h] = gather(x) @ w[e]  ----------------
// 128x128x8 tile, 256 threads, 8x8 microtile. which=0 -> hbuf, which=1 -> gbuf.
__global__ __launch_bounds__(256, 2)
void gemm1_kernel(const float* __restrict__ x, const float* __restrict__ w, int which) {
    int e   = blockIdx.z;
    int cnt = g_counts[e];
    int m0  = blockIdx.y * 128;
    if (m0 >= cnt) return;
    int off = g_offsets[e];
    int n0  = blockIdx.x * 128;
    const float* wB  = w + (size_t)e * DD * HH;
    float*       dst = which ? g_gbuf : g_hbuf;

    __shared__ float As[8][128];
    __shared__ float Bs[8][128];
    __shared__ int   rowbase[128];

    int tid = threadIdx.x;
    if (tid < 128) {
        int m = m0 + tid;
        rowbase[tid] = (m < cnt) ? g_tok[off + m] * DD : 0;
    }
    __syncthreads();

    int tx = tid & 15, ty = tid >> 4;
    float acc[8][8];
    #pragma unroll
    for (int i = 0; i < 8; i++)
        #pragma unroll
        for (int j = 0; j < 8; j++) acc[i][j] = 0.0f;

    int aRow = tid >> 1, aCol = (tid & 1) * 4;
    int bRow = tid >> 5, bCol = (tid & 31) * 4;

    for (int kk = 0; kk < DD; kk += 8) {
        float4 av = *(const float4*)(x + rowbase[aRow] + kk + aCol);
        As[aCol + 0][aRow] = av.x;
        As[aCol + 1][aRow] = av.y;
        As[aCol + 2][aRow] = av.z;
        As[aCol + 3][aRow] = av.w;
        float4 bv = *(const float4*)(wB + (size_t)(kk + bRow) * HH + n0 + bCol);
        *(float4*)(&Bs[bRow][bCol]) = bv;
        __syncthreads();
        #pragma unroll
        for (int k = 0; k < 8; k++) {
            float ar[8], br[8];
            *(float4*)(ar)     = *(const float4*)(&As[k][ty * 8]);
            *(float4*)(ar + 4) = *(const float4*)(&As[k][ty * 8 + 4]);
            *(float4*)(br)     = *(const float4*)(&Bs[k][tx * 8]);
            *(float4*)(br + 4) = *(const float4*)(&Bs[k][tx * 8 + 4]);
            #pragma unroll
            for (int i = 0; i < 8; i++)
                #pragma unroll
                for (int j = 0; j < 8; j++)
                    acc[i][j] += ar[i] * br[j];
        }
        __syncthreads();
    }
    #pragma unroll
    for (int i = 0; i < 8; i++) {
        int m = m0 + ty * 8 + i;
        if (m < cnt) {
            float* drow = dst + (size_t)(off + m) * HH + n0 + tx * 8;
            *(float4*)(drow)     = make_float4(acc[i][0], acc[i][1], acc[i][2], acc[i][3]);
            *(float4*)(drow + 4) = make_float4(acc[i][4], acc[i][5], acc[i][6], acc[i][7]);
        }
    }
}

// ---------------- 6: GEMM2  out[tok] += wt * (silu(h)*g) @ w2[e] --------------
__device__ __forceinline__ float silu_mul(float h, float g) {
    return (h / (1.0f + expf(-h))) * g;
}

__global__ __launch_bounds__(256, 2)
void gemm2_kernel(const float* __restrict__ w2, float* __restrict__ out) {
    int e   = blockIdx.z;
    int cnt = g_counts[e];
    int m0  = blockIdx.y * 128;
    if (m0 >= cnt) return;
    int off = g_offsets[e];
    int n0  = blockIdx.x * 128;
    const float* wB = w2 + (size_t)e * HH * DD;

    __shared__ float As[8][128];
    __shared__ float Bs[8][128];
    __shared__ int   tokof[128];
    __shared__ float wts[128];

    int tid = threadIdx.x;
    if (tid < 128) {
        int m = m0 + tid;
        bool v = (m < cnt);
        tokof[tid] = v ? g_tok[off + m] * DD : 0;
        wts[tid]   = v ? g_wt[off + m] : 0.0f;
    }
    __syncthreads();

    int tx = tid & 15, ty = tid >> 4;
    float acc[8][8];
    #pragma unroll
    for (int i = 0; i < 8; i++)
        #pragma unroll
        for (int j = 0; j < 8; j++) acc[i][j] = 0.0f;

    int aRow = tid >> 1, aCol = (tid & 1) * 4;
    int bRow = tid >> 5, bCol = (tid & 31) * 4;

    int slotRow = off + m0 + aRow;
    if (slotRow > TKS - 1) slotRow = TKS - 1;       // clamp (tail tile of last expert)
    size_t abase = (size_t)slotRow * HH + aCol;

    for (int kk = 0; kk < HH; kk += 8) {
        float4 hv = *(const float4*)(g_hbuf + abase + kk);
        float4 gv = *(const float4*)(g_gbuf + abase + kk);
        As[aCol + 0][aRow] = silu_mul(hv.x, gv.x);
        As[aCol + 1][aRow] = silu_mul(hv.y, gv.y);
        As[aCol + 2][aRow] = silu_mul(hv.z, gv.z);
        As[aCol + 3][aRow] = silu_mul(hv.w, gv.w);
        float4 bv = *(const float4*)(wB + (size_t)(kk + bRow) * DD + n0 + bCol);
        *(float4*)(&Bs[bRow][bCol]) = bv;
        __syncthreads();
        #pragma unroll
        for (int k = 0; k < 8; k++) {
            float ar[8], br[8];
            *(float4*)(ar)     = *(const float4*)(&As[k][ty * 8]);
            *(float4*)(ar + 4) = *(const float4*)(&As[k][ty * 8 + 4]);
            *(float4*)(br)     = *(const float4*)(&Bs[k][tx * 8]);
            *(float4*)(br + 4) = *(const float4*)(&Bs[k][tx * 8 + 4]);
            #pragma unroll
            for (int i = 0; i < 8; i++)
                #pragma unroll
                for (int j = 0; j < 8; j++)
                    acc[i][j] += ar[i] * br[j];
        }
        __syncthreads();
    }
    #pragma unroll
    for (int i = 0; i < 8; i++) {
        int m = m0 + ty * 8 + i;
        if (m < cnt) {
            float wgt   = wts[ty * 8 + i];
            float* orow = out + tokof[ty * 8 + i] + n0 + tx * 8;
            #pragma unroll
            for (int j = 0; j < 8; j++)
                atomicAdd(orow + j, wgt * acc[i][j]);
        }
    }
}

// ---------------- launch ------------------------------------------------------
extern "C" void kernel_launch(void* const* d_in, const int* in_sizes, int n_in,
                              void* d_out, int out_size) {
    const float* x    = (const float*)d_in[0];
    const float* gw   = (const float*)d_in[1];
    const float* bias = (const float*)d_in[2];
    const float* w1   = (const float*)d_in[3];
    const float* w3   = (const float*)d_in[4];
    const float* w2   = (const float*)d_in[5];
    float* out = (float*)d_out;

    int nz = (out_size + 255) / 256;
    zero_kernel<<<nz, 256>>>(out, out_size);
    router_kernel<<<TT, 128>>>(x, gw, bias);
    scan_kernel<<<1, 32>>>(out, out_size);
    scatter_kernel<<<TKS / 256, 256>>>();

    dim3 g1(HH / 128, TT / 128, EE);   // (8, 16, 16)
    gemm1_kernel<<<g1, 256>>>(x, w1, 0);   // -> g_hbuf
    gemm1_kernel<<<g1, 256>>>(x, w3, 1);   // -> g_gbuf

    dim3 g2(DD / 128, TT / 128, EE);   // (8, 16, 16)
    gemm2_kernel<<<g2, 256>>>(w2, out);
}

// round 4
// speedup vs baseline: 2.0375x; 2.0375x over previous
#include <cuda_runtime.h>
#include <math.h>
#include <stdint.h>

#define TT   2048
#define DD   1024
#define EE   16
#define HH   1024
#define KK   4
#define TKS  (TT*KK)
#define EPSF 1e-6f

// ---------------- device scratch (static; no cudaMalloc) --------------------
__device__ float g_ssum[EE];
__device__ int   g_counts[EE];
__device__ int   g_offsets[EE];
__device__ int   g_fill[EE];
__device__ int   g_tok[TKS];
__device__ int   g_slot[TKS];
__device__ int   g_topk_e[TKS];
__device__ float g_topk_w[TKS];
__device__ float g_hbuf[(size_t)TKS * HH];
__device__ float g_gbuf[(size_t)TKS * HH];
__device__ float g_ybuf[(size_t)TKS * DD];

// ---------------- tf32 helpers ------------------------------------------------
__device__ __forceinline__ uint32_t f2tf(float f) {
    uint32_t u;
    asm("cvt.rna.tf32.f32 %0, %1;" : "=r"(u) : "f"(f));
    return u;
}
#define MMA_TF32(c, a, b0, b1) \
  asm volatile("mma.sync.aligned.m16n8k8.row.col.f32.tf32.tf32.f32 " \
    "{%0,%1,%2,%3}, {%4,%5,%6,%7}, {%8,%9}, {%0,%1,%2,%3};" \
    : "+f"((c)[0]), "+f"((c)[1]), "+f"((c)[2]), "+f"((c)[3]) \
    : "r"((a)[0]), "r"((a)[1]), "r"((a)[2]), "r"((a)[3]), "r"(b0), "r"(b1))

__device__ __forceinline__ float silu_mul(float h, float g) {
    return (h / (1.0f + expf(-h))) * g;
}

// SMEM layout (uint32 elements), double buffered:
//   AS[buf][128][36]   at 0        (A tile, row-major, 36-pad)
//   BS[buf][32][68]    at 9216     (B tile, k-major rows, 68-pad)
#define AS_IDX(buf, m, k) ((buf) * 4608 + (m) * 36 + (k))
#define BS_IDX(buf, k, n) (9216 + (buf) * 2176 + (k) * 68 + (n))
#define SMEM_SZ (13568 * 4)

// ---------------- 0: init ------------------------------------------------------
__global__ void init_kernel(float* __restrict__ out, int out_size) {
    int i = blockIdx.x * blockDim.x + threadIdx.x;
    if (i < EE) { g_counts[i] = 0; g_ssum[i] = 0.0f; g_fill[i] = 0; }
    int t = TT * DD + i;
    if (t < out_size) out[t] = 0.0f;
}

// ---------------- 1: router (exact fp32) --------------------------------------
__global__ void router_kernel(const float* __restrict__ x,
                              const float* __restrict__ gw,
                              const float* __restrict__ bias) {
    int t = blockIdx.x;
    __shared__ float xs[DD];
    __shared__ float logits[EE];
    __shared__ float scores[EE];
    int tid = threadIdx.x;
    for (int d = tid; d < DD; d += 128) xs[d] = x[t * DD + d];
    __syncthreads();

    int warp = tid >> 5, lane = tid & 31;
    for (int e = warp; e < EE; e += 4) {
        float s = 0.0f;
        for (int d = lane; d < DD; d += 32) s += xs[d] * gw[d * EE + e];
        #pragma unroll
        for (int o = 16; o; o >>= 1) s += __shfl_down_sync(0xffffffff, s, o);
        if (lane == 0) logits[e] = s + bias[e];
    }
    __syncthreads();

    if (tid == 0) {
        float ssum = 0.0f;
        #pragma unroll
        for (int e = 0; e < EE; e++) {
            float sc = 1.0f / (1.0f + expf(-logits[e]));
            scores[e] = sc; ssum += sc;
        }
        float inv = 1.0f / (ssum + EPSF);
        #pragma unroll
        for (int e = 0; e < EE; e++) {
            scores[e] *= inv;
            atomicAdd(&g_ssum[e], scores[e]);
        }
        unsigned used = 0u;
        int idx[KK]; float val[KK]; float wsum = 0.0f;
        #pragma unroll
        for (int k = 0; k < KK; k++) {
            float best = -1e30f; int bi = 0;
            #pragma unroll
            for (int e = 0; e < EE; e++)
                if (!((used >> e) & 1u) && scores[e] > best) { best = scores[e]; bi = e; }
            used |= (1u << bi);
            idx[k] = bi; val[k] = best; wsum += best;
        }
        float winv = 1.0f / (wsum + EPSF);
        #pragma unroll
        for (int k = 0; k < KK; k++) {
            g_topk_e[t * KK + k] = idx[k];
            g_topk_w[t * KK + k] = val[k] * winv;
            atomicAdd(&g_counts[idx[k]], 1);
        }
    }
}

// ---------------- 2: scan + lb loss --------------------------------------------
__global__ void scan_kernel(float* __restrict__ out, int out_size) {
    if (threadIdx.x == 0 && blockIdx.x == 0) {
        int off = 0;
        #pragma unroll
        for (int e = 0; e < EE; e++) { g_offsets[e] = off; off += g_counts[e]; }
        float lb = 0.0f;
        #pragma unroll
        for (int e = 0; e < EE; e++) lb += (float)g_counts[e] * g_ssum[e];
        lb *= (float)EE / ((float)TT * (float)TT);
        if (out_size > TT * DD) out[TT * DD] = lb;
    }
}

// ---------------- 3: scatter ----------------------------------------------------
__global__ void scatter_kernel() {
    int i = blockIdx.x * blockDim.x + threadIdx.x;
    if (i >= TKS) return;
    int t = i >> 2;
    int e = g_topk_e[i];
    int pos = atomicAdd(&g_fill[e], 1);
    int slot = g_offsets[e] + pos;
    g_tok[slot] = t;
    g_slot[i]   = slot;
}

// ---------------- 4: GEMM1 (mma.sync tf32): dst = gather(x) @ W ----------------
// CTA 128x64, KT=32, 8 warps (4m x 2n), warp tile 32x32.
// which=0 -> g_hbuf, which=1 -> g_gbuf  (device globals referenced IN DEVICE CODE)
__global__ __launch_bounds__(256, 2)
void gemm1_tc(const float* __restrict__ x, const float* __restrict__ w, int which) {
    int e   = blockIdx.z;
    int cnt = g_counts[e];
    int m0  = blockIdx.y * 128;
    if (m0 >= cnt) return;
    int off = g_offsets[e];
    int n0  = blockIdx.x * 64;
    const float* wB  = w + (size_t)e * DD * HH;
    float*       dst = which ? g_gbuf : g_hbuf;

    extern __shared__ uint32_t sm[];
    __shared__ int rowb[128];

    int tid = threadIdx.x;
    if (tid < 128) {
        int m = m0 + tid;
        rowb[tid] = g_tok[off + (m < cnt ? m : cnt - 1)] * DD;
    }
    __syncthreads();

    int wid = tid >> 5, lane = tid & 31;
    int grp = lane >> 2, tig = lane & 3;
    int wm = wid & 3, wn = wid >> 2;

    float acc[2][4][4];
    #pragma unroll
    for (int i = 0; i < 2; i++)
        #pragma unroll
        for (int j = 0; j < 4; j++)
            #pragma unroll
            for (int q = 0; q < 4; q++) acc[i][j][q] = 0.0f;

    int arow[4], acol[4], brow[2], bcol[2];
    #pragma unroll
    for (int f = 0; f < 4; f++) { int id = tid + 256 * f; arow[f] = id >> 3; acol[f] = (id & 7) * 4; }
    #pragma unroll
    for (int f = 0; f < 2; f++) { int id = tid + 256 * f; brow[f] = id >> 4; bcol[f] = (id & 15) * 4; }

    float4 ra[4], rb[2];

    // prologue: k-tile 0
    #pragma unroll
    for (int f = 0; f < 4; f++) ra[f] = *(const float4*)(x + rowb[arow[f]] + acol[f]);
    #pragma unroll
    for (int f = 0; f < 2; f++) rb[f] = *(const float4*)(wB + (size_t)brow[f] * HH + n0 + bcol[f]);
    #pragma unroll
    for (int f = 0; f < 4; f++) {
        uint4 v = make_uint4(f2tf(ra[f].x), f2tf(ra[f].y), f2tf(ra[f].z), f2tf(ra[f].w));
        *(uint4*)&sm[AS_IDX(0, arow[f], acol[f])] = v;
    }
    #pragma unroll
    for (int f = 0; f < 2; f++) {
        uint4 v = make_uint4(f2tf(rb[f].x), f2tf(rb[f].y), f2tf(rb[f].z), f2tf(rb[f].w));
        *(uint4*)&sm[BS_IDX(0, brow[f], bcol[f])] = v;
    }
    __syncthreads();

    for (int c = 0; c < DD / 32; c++) {
        int cur = c & 1;
        if (c + 1 < DD / 32) {
            int k0 = (c + 1) * 32;
            #pragma unroll
            for (int f = 0; f < 4; f++) ra[f] = *(const float4*)(x + rowb[arow[f]] + k0 + acol[f]);
            #pragma unroll
            for (int f = 0; f < 2; f++) rb[f] = *(const float4*)(wB + (size_t)(k0 + brow[f]) * HH + n0 + bcol[f]);
        }
        #pragma unroll
        for (int s = 0; s < 4; s++) {
            uint32_t afr[2][4];
            #pragma unroll
            for (int i = 0; i < 2; i++) {
                int r = wm * 32 + i * 16;
                afr[i][0] = sm[AS_IDX(cur, r + grp,     s * 8 + tig)];
                afr[i][1] = sm[AS_IDX(cur, r + grp + 8, s * 8 + tig)];
                afr[i][2] = sm[AS_IDX(cur, r + grp,     s * 8 + tig + 4)];
                afr[i][3] = sm[AS_IDX(cur, r + grp + 8, s * 8 + tig + 4)];
            }
            #pragma unroll
            for (int j = 0; j < 4; j++) {
                uint32_t b0 = sm[BS_IDX(cur, s * 8 + tig,     wn * 32 + j * 8 + grp)];
                uint32_t b1 = sm[BS_IDX(cur, s * 8 + tig + 4, wn * 32 + j * 8 + grp)];
                MMA_TF32(acc[0][j], afr[0], b0, b1);
                MMA_TF32(acc[1][j], afr[1], b0, b1);
            }
        }
        if (c + 1 < DD / 32) {
            int nb = (c + 1) & 1;
            #pragma unroll
            for (int f = 0; f < 4; f++) {
                uint4 v = make_uint4(f2tf(ra[f].x), f2tf(ra[f].y), f2tf(ra[f].z), f2tf(ra[f].w));
                *(uint4*)&sm[AS_IDX(nb, arow[f], acol[f])] = v;
            }
            #pragma unroll
            for (int f = 0; f < 2; f++) {
                uint4 v = make_uint4(f2tf(rb[f].x), f2tf(rb[f].y), f2tf(rb[f].z), f2tf(rb[f].w));
                *(uint4*)&sm[BS_IDX(nb, brow[f], bcol[f])] = v;
            }
            __syncthreads();
        }
    }

    #pragma unroll
    for (int i = 0; i < 2; i++) {
        int r0 = m0 + wm * 32 + i * 16 + grp;
        #pragma unroll
        for (int j = 0; j < 4; j++) {
            int cbase = n0 + wn * 32 + j * 8 + tig * 2;
            if (r0 < cnt)
                *(float2*)(dst + (size_t)(off + r0) * HH + cbase) = make_float2(acc[i][j][0], acc[i][j][1]);
            if (r0 + 8 < cnt)
                *(float2*)(dst + (size_t)(off + r0 + 8) * HH + cbase) = make_float2(acc[i][j][2], acc[i][j][3]);
        }
    }
}

// ---------------- 5: GEMM2 (mma.sync tf32): ybuf = silu(h)*g @ W2 --------------
__global__ __launch_bounds__(256, 2)
void gemm2_tc(const float* __restrict__ w2) {
    int e   = blockIdx.z;
    int cnt = g_counts[e];
    int m0  = blockIdx.y * 128;
    if (m0 >= cnt) return;
    int off = g_offsets[e];
    int n0  = blockIdx.x * 64;
    const float* wB = w2 + (size_t)e * HH * DD;

    extern __shared__ uint32_t sm[];
    __shared__ int srow[128];

    int tid = threadIdx.x;
    if (tid < 128) {
        int s = off + m0 + tid;
        if (s > TKS - 1) s = TKS - 1;
        srow[tid] = s;
    }
    __syncthreads();

    int wid = tid >> 5, lane = tid & 31;
    int grp = lane >> 2, tig = lane & 3;
    int wm = wid & 3, wn = wid >> 2;

    float acc[2][4][4];
    #pragma unroll
    for (int i = 0; i < 2; i++)
        #pragma unroll
        for (int j = 0; j < 4; j++)
            #pragma unroll
            for (int q = 0; q < 4; q++) acc[i][j][q] = 0.0f;

    int arow[4], acol[4], brow[2], bcol[2];
    #pragma unroll
    for (int f = 0; f < 4; f++) { int id = tid + 256 * f; arow[f] = id >> 3; acol[f] = (id & 7) * 4; }
    #pragma unroll
    for (int f = 0; f < 2; f++) { int id = tid + 256 * f; brow[f] = id >> 4; bcol[f] = (id & 15) * 4; }

    float4 rh[4], rg[4], rb[2];

    // prologue
    #pragma unroll
    for (int f = 0; f < 4; f++) {
        size_t base = (size_t)srow[arow[f]] * HH + acol[f];
        rh[f] = *(const float4*)(g_hbuf + base);
        rg[f] = *(const float4*)(g_gbuf + base);
    }
    #pragma unroll
    for (int f = 0; f < 2; f++) rb[f] = *(const float4*)(wB + (size_t)brow[f] * DD + n0 + bcol[f]);
    #pragma unroll
    for (int f = 0; f < 4; f++) {
        uint4 v = make_uint4(f2tf(silu_mul(rh[f].x, rg[f].x)), f2tf(silu_mul(rh[f].y, rg[f].y)),
                             f2tf(silu_mul(rh[f].z, rg[f].z)), f2tf(silu_mul(rh[f].w, rg[f].w)));
        *(uint4*)&sm[AS_IDX(0, arow[f], acol[f])] = v;
    }
    #pragma unroll
    for (int f = 0; f < 2; f++) {
        uint4 v = make_uint4(f2tf(rb[f].x), f2tf(rb[f].y), f2tf(rb[f].z), f2tf(rb[f].w));
        *(uint4*)&sm[BS_IDX(0, brow[f], bcol[f])] = v;
    }
    __syncthreads();

    for (int c = 0; c < HH / 32; c++) {
        int cur = c & 1;
        if (c + 1 < HH / 32) {
            int k0 = (c + 1) * 32;
            #pragma unroll
            for (int f = 0; f < 4; f++) {
                size_t base = (size_t)srow[arow[f]] * HH + k0 + acol[f];
                rh[f] = *(const float4*)(g_hbuf + base);
                rg[f] = *(const float4*)(g_gbuf + base);
            }
            #pragma unroll
            for (int f = 0; f < 2; f++) rb[f] = *(const float4*)(wB + (size_t)(k0 + brow[f]) * DD + n0 + bcol[f]);
        }
        #pragma unroll
        for (int s = 0; s < 4; s++) {
            uint32_t afr[2][4];
            #pragma unroll
            for (int i = 0; i < 2; i++) {
                int r = wm * 32 + i * 16;
                afr[i][0] = sm[AS_IDX(cur, r + grp,     s * 8 + tig)];
                afr[i][1] = sm[AS_IDX(cur, r + grp + 8, s * 8 + tig)];
                afr[i][2] = sm[AS_IDX(cur, r + grp,     s * 8 + tig + 4)];
                afr[i][3] = sm[AS_IDX(cur, r + grp + 8, s * 8 + tig + 4)];
            }
            #pragma unroll
            for (int j = 0; j < 4; j++) {
                uint32_t b0 = sm[BS_IDX(cur, s * 8 + tig,     wn * 32 + j * 8 + grp)];
                uint32_t b1 = sm[BS_IDX(cur, s * 8 + tig + 4, wn * 32 + j * 8 + grp)];
                MMA_TF32(acc[0][j], afr[0], b0, b1);
                MMA_TF32(acc[1][j], afr[1], b0, b1);
            }
        }
        if (c + 1 < HH / 32) {
            int nb = (c + 1) & 1;
            #pragma unroll
            for (int f = 0; f < 4; f++) {
                uint4 v = make_uint4(f2tf(silu_mul(rh[f].x, rg[f].x)), f2tf(silu_mul(rh[f].y, rg[f].y)),
                                     f2tf(silu_mul(rh[f].z, rg[f].z)), f2tf(silu_mul(rh[f].w, rg[f].w)));
                *(uint4*)&sm[AS_IDX(nb, arow[f], acol[f])] = v;
            }
            #pragma unroll
            for (int f = 0; f < 2; f++) {
                uint4 v = make_uint4(f2tf(rb[f].x), f2tf(rb[f].y), f2tf(rb[f].z), f2tf(rb[f].w));
                *(uint4*)&sm[BS_IDX(nb, brow[f], bcol[f])] = v;
            }
            __syncthreads();
        }
    }

    #pragma unroll
    for (int i = 0; i < 2; i++) {
        int r0 = m0 + wm * 32 + i * 16 + grp;
        #pragma unroll
        for (int j = 0; j < 4; j++) {
            int cbase = n0 + wn * 32 + j * 8 + tig * 2;
            if (r0 < cnt)
                *(float2*)(g_ybuf + (size_t)(off + r0) * DD + cbase) = make_float2(acc[i][j][0], acc[i][j][1]);
            if (r0 + 8 < cnt)
                *(float2*)(g_ybuf + (size_t)(off + r0 + 8) * DD + cbase) = make_float2(acc[i][j][2], acc[i][j][3]);
        }
    }
}

// ---------------- 6: combine ----------------------------------------------------
__global__ void combine_kernel(float* __restrict__ out) {
    int id = blockIdx.x * blockDim.x + threadIdx.x;
    int t  = id >> 8;
    int d4 = (id & 255) * 4;
    float4 acc = make_float4(0.f, 0.f, 0.f, 0.f);
    #pragma unroll
    for (int k = 0; k < KK; k++) {
        int   slot = g_slot[t * KK + k];
        float w    = g_topk_w[t * KK + k];
        float4 v = *(const float4*)(g_ybuf + (size_t)slot * DD + d4);
        acc.x += w * v.x; acc.y += w * v.y; acc.z += w * v.z; acc.w += w * v.w;
    }
    *(float4*)(out + (size_t)t * DD + d4) = acc;
}

// ---------------- launch ---------------------------------------------------------
extern "C" void kernel_launch(void* const* d_in, const int* in_sizes, int n_in,
                              void* d_out, int out_size) {
    const float* x    = (const float*)d_in[0];
    const float* gw   = (const float*)d_in[1];
    const float* bias = (const float*)d_in[2];
    const float* w1   = (const float*)d_in[3];
    const float* w3   = (const float*)d_in[4];
    const float* w2   = (const float*)d_in[5];
    float* out = (float*)d_out;

    cudaFuncSetAttribute(gemm1_tc, cudaFuncAttributeMaxDynamicSharedMemorySize, SMEM_SZ);
    cudaFuncSetAttribute(gemm2_tc, cudaFuncAttributeMaxDynamicSharedMemorySize, SMEM_SZ);

    int tail = out_size - TT * DD;
    int nb = (tail + EE + 255) / 256; if (nb < 1) nb = 1;
    init_kernel<<<nb, 256>>>(out, out_size);
    router_kernel<<<TT, 128>>>(x, gw, bias);
    scan_kernel<<<1, 32>>>(out, out_size);
    scatter_kernel<<<TKS / 256, 256>>>();

    dim3 g1(HH / 64, TT / 128, EE);   // (16, 16, 16)
    gemm1_tc<<<g1, 256, SMEM_SZ>>>(x, w1, 0);   // -> g_hbuf
    gemm1_tc<<<g1, 256, SMEM_SZ>>>(x, w3, 1);   // -> g_gbuf

    dim3 g2(DD / 64, TT / 128, EE);   // (16, 16, 16)
    gemm2_tc<<<g2, 256, SMEM_SZ>>>(w2);

    combine_kernel<<<(TT * DD / 4) / 256, 256>>>(out);
}

// round 5
// speedup vs baseline: 3.1057x; 1.5243x over previous
#include <cuda_runtime.h>
#include <math.h>
#include <stdint.h>

#define TT   2048
#define DD   1024
#define EE   16
#define HH   1024
#define KK   4
#define TKS  (TT*KK)
#define NWE  (DD*HH)          // weights per expert (1M)
#define NW   (EE*NWE)         // 16M per weight tensor
#define EPSF 1e-6f

// ---------------- device scratch (static; no cudaMalloc) --------------------
__device__ float g_ssum[EE];
__device__ int   g_counts[EE];
__device__ int   g_offsets[EE];
__device__ int   g_fill[EE];
__device__ int   g_tok[TKS];
__device__ int   g_slot[TKS];
__device__ int   g_topk_e[TKS];
__device__ float g_topk_w[TKS];
__device__ float g_xr [(size_t)TT * DD];     // x rounded to tf32
__device__ float g_w1r[(size_t)NW];          // weights rounded to tf32
__device__ float g_w3r[(size_t)NW];
__device__ float g_w2r[(size_t)NW];
__device__ float g_abuf[(size_t)TKS * HH];   // silu(x@w1)*(x@w3), tf32-rounded
__device__ float g_ybuf[(size_t)TKS * DD];

// ---------------- helpers ------------------------------------------------------
__device__ __forceinline__ uint32_t f2tf(float f) {
    uint32_t u;
    asm("cvt.rna.tf32.f32 %0, %1;" : "=r"(u) : "f"(f));
    return u;
}
__device__ __forceinline__ uint4 r4(float4 a) {
    return make_uint4(f2tf(a.x), f2tf(a.y), f2tf(a.z), f2tf(a.w));
}
#define MMA_TF32(c, a, b0, b1) \
  asm volatile("mma.sync.aligned.m16n8k8.row.col.f32.tf32.tf32.f32 " \
    "{%0,%1,%2,%3}, {%4,%5,%6,%7}, {%8,%9}, {%0,%1,%2,%3};" \
    : "+f"((c)[0]), "+f"((c)[1]), "+f"((c)[2]), "+f"((c)[3]) \
    : "r"((a)[0]), "r"((a)[1]), "r"((a)[2]), "r"((a)[3]), "r"(b0), "r"(b1))

__device__ __forceinline__ float silu_mul(float h, float g) {
    return (h / (1.0f + expf(-h))) * g;
}
__device__ __forceinline__ uint32_t smem_u32(const void* p) {
    uint32_t r;
    asm("{ .reg .u64 t; cvta.to.shared.u64 t, %1; cvt.u32.u64 %0, t; }" : "=r"(r) : "l"(p));
    return r;
}
__device__ __forceinline__ void cp16(uint32_t d, const void* s) {
    asm volatile("cp.async.cg.shared.global [%0], [%1], 16;" :: "r"(d), "l"(s));
}
__device__ __forceinline__ void cp_commit() { asm volatile("cp.async.commit_group;" ::: "memory"); }
template<int N>
__device__ __forceinline__ void cp_wait() { asm volatile("cp.async.wait_group %0;" :: "n"(N) : "memory"); }

// SMEM layouts in floats.
// gemm13 stage = A[128][36] + B1[32][72] + B3[32][72] = 9216 floats; 2 stages.
#define G13_A(s,m,k)  ((s)*9216 + (m)*36 + (k))
#define G13_B1(s,k,n) ((s)*9216 + 4608 + (k)*72 + (n))
#define G13_B3(s,k,n) ((s)*9216 + 6912 + (k)*72 + (n))
#define SMEM13 (2 * 9216 * 4)
// gemm2 stage = A[128][36] + B[32][72] = 6912 floats; 3 stages.
#define G2_A(s,m,k)   ((s)*6912 + (m)*36 + (k))
#define G2_B(s,k,n)   ((s)*6912 + 4608 + (k)*72 + (n))
#define SMEM2 (3 * 6912 * 4)

// ---------------- convert: round weights + x to tf32 once per call -------------
__global__ void convert_kernel(const float* __restrict__ w1, const float* __restrict__ w3,
                               const float* __restrict__ w2, const float* __restrict__ x) {
    size_t stride = (size_t)gridDim.x * blockDim.x;
    size_t tid = (size_t)blockIdx.x * blockDim.x + threadIdx.x;
    const float4* w1v = (const float4*)w1;
    const float4* w3v = (const float4*)w3;
    const float4* w2v = (const float4*)w2;
    uint4* d1 = (uint4*)g_w1r; uint4* d3 = (uint4*)g_w3r; uint4* d2 = (uint4*)g_w2r;
    for (size_t i = tid; i < NW / 4; i += stride) {
        d1[i] = r4(w1v[i]);
        d3[i] = r4(w3v[i]);
        d2[i] = r4(w2v[i]);
    }
    const float4* xv = (const float4*)x;
    uint4* dx = (uint4*)g_xr;
    for (size_t i = tid; i < (size_t)TT * DD / 4; i += stride)
        dx[i] = r4(xv[i]);
}

// ---------------- init ----------------------------------------------------------
__global__ void init_kernel(float* __restrict__ out, int out_size) {
    int i = blockIdx.x * blockDim.x + threadIdx.x;
    if (i < EE) { g_counts[i] = 0; g_ssum[i] = 0.0f; g_fill[i] = 0; }
    int t = TT * DD + i;
    if (t < out_size) out[t] = 0.0f;
}

// ---------------- router (exact fp32) -------------------------------------------
__global__ void router_kernel(const float* __restrict__ x,
                              const float* __restrict__ gw,
                              const float* __restrict__ bias) {
    int t = blockIdx.x;
    __shared__ float xs[DD];
    __shared__ float logits[EE];
    __shared__ float scores[EE];
    int tid = threadIdx.x;
    for (int d = tid; d < DD; d += 128) xs[d] = x[t * DD + d];
    __syncthreads();

    int warp = tid >> 5, lane = tid & 31;
    for (int e = warp; e < EE; e += 4) {
        float s = 0.0f;
        for (int d = lane; d < DD; d += 32) s += xs[d] * gw[d * EE + e];
        #pragma unroll
        for (int o = 16; o; o >>= 1) s += __shfl_down_sync(0xffffffff, s, o);
        if (lane == 0) logits[e] = s + bias[e];
    }
    __syncthreads();

    if (tid == 0) {
        float ssum = 0.0f;
        #pragma unroll
        for (int e = 0; e < EE; e++) {
            float sc = 1.0f / (1.0f + expf(-logits[e]));
            scores[e] = sc; ssum += sc;
        }
        float inv = 1.0f / (ssum + EPSF);
        #pragma unroll
        for (int e = 0; e < EE; e++) {
            scores[e] *= inv;
            atomicAdd(&g_ssum[e], scores[e]);
        }
        unsigned used = 0u;
        int idx[KK]; float val[KK]; float wsum = 0.0f;
        #pragma unroll
        for (int k = 0; k < KK; k++) {
            float best = -1e30f; int bi = 0;
            #pragma unroll
            for (int e = 0; e < EE; e++)
                if (!((used >> e) & 1u) && scores[e] > best) { best = scores[e]; bi = e; }
            used |= (1u << bi);
            idx[k] = bi; val[k] = best; wsum += best;
        }
        float winv = 1.0f / (wsum + EPSF);
        #pragma unroll
        for (int k = 0; k < KK; k++) {
            g_topk_e[t * KK + k] = idx[k];
            g_topk_w[t * KK + k] = val[k] * winv;
            atomicAdd(&g_counts[idx[k]], 1);
        }
    }
}

// ---------------- scan + lb loss -------------------------------------------------
__global__ void scan_kernel(float* __restrict__ out, int out_size) {
    if (threadIdx.x == 0 && blockIdx.x == 0) {
        int off = 0;
        #pragma unroll
        for (int e = 0; e < EE; e++) { g_offsets[e] = off; off += g_counts[e]; }
        float lb = 0.0f;
        #pragma unroll
        for (int e = 0; e < EE; e++) lb += (float)g_counts[e] * g_ssum[e];
        lb *= (float)EE / ((float)TT * (float)TT);
        if (out_size > TT * DD) out[TT * DD] = lb;
    }
}

// ---------------- scatter --------------------------------------------------------
__global__ void scatter_kernel() {
    int i = blockIdx.x * blockDim.x + threadIdx.x;
    if (i >= TKS) return;
    int t = i >> 2;
    int e = g_topk_e[i];
    int pos = atomicAdd(&g_fill[e], 1);
    int slot = g_offsets[e] + pos;
    g_tok[slot] = t;
    g_slot[i]   = slot;
}

// ---------------- gemm13 fills ----------------------------------------------------
__device__ __forceinline__ void fill13(uint32_t sbase, int st, int c, int tid,
                                       const int* rowb, const float* w1e,
                                       const float* w3e, int n0) {
    int k0 = c * 32;
    #pragma unroll
    for (int f = 0; f < 4; f++) {
        int id = tid + 256 * f;
        int m = id >> 3, k4 = (id & 7) * 4;
        cp16(sbase + G13_A(st, m, k4) * 4, g_xr + rowb[m] + k0 + k4);
    }
    #pragma unroll
    for (int f = 0; f < 2; f++) {
        int id = tid + 256 * f;
        int k = id >> 4, n4 = (id & 15) * 4;
        size_t gofs = (size_t)(k0 + k) * HH + n0 + n4;
        cp16(sbase + G13_B1(st, k, n4) * 4, w1e + gofs);
        cp16(sbase + G13_B3(st, k, n4) * 4, w3e + gofs);
    }
}

// ---------------- GEMM13: abuf = silu(gather(x)@W1) * (gather(x)@W3) -------------
// CTA 128(M) x 64(N), KT=32, 2-stage cp.async, 8 warps, warp tile 32x32 x 2 mats.
__global__ __launch_bounds__(256, 2)
void gemm13_tc() {
    int e   = blockIdx.z;
    int cnt = g_counts[e];
    int m0  = blockIdx.y * 128;
    if (m0 >= cnt) return;
    int off = g_offsets[e];
    int n0  = blockIdx.x * 64;
    const float* w1e = g_w1r + (size_t)e * NWE;
    const float* w3e = g_w3r + (size_t)e * NWE;

    extern __shared__ float sm[];
    uint32_t* smu = (uint32_t*)sm;
    uint32_t sbase = smem_u32(sm);
    __shared__ int rowb[128];

    int tid = threadIdx.x;
    if (tid < 128) {
        int m = m0 + tid;
        rowb[tid] = g_tok[off + (m < cnt ? m : cnt - 1)] * DD;
    }
    __syncthreads();

    int wid = tid >> 5, lane = tid & 31;
    int grp = lane >> 2, tig = lane & 3;
    int wm = wid & 3, wn = wid >> 2;

    float accH[2][4][4], accG[2][4][4];
    #pragma unroll
    for (int i = 0; i < 2; i++)
        #pragma unroll
        for (int j = 0; j < 4; j++)
            #pragma unroll
            for (int q = 0; q < 4; q++) { accH[i][j][q] = 0.0f; accG[i][j][q] = 0.0f; }

    fill13(sbase, 0, 0, tid, rowb, w1e, w3e, n0);
    cp_commit();

    for (int c = 0; c < DD / 32; c++) {
        cp_wait<0>();
        __syncthreads();
        if (c + 1 < DD / 32)
            fill13(sbase, (c + 1) & 1, c + 1, tid, rowb, w1e, w3e, n0);
        cp_commit();

        int sl = c & 1;
        #pragma unroll
        for (int s = 0; s < 4; s++) {
            uint32_t afr[2][4];
            #pragma unroll
            for (int i = 0; i < 2; i++) {
                int r = wm * 32 + i * 16;
                afr[i][0] = smu[G13_A(sl, r + grp,     s * 8 + tig)];
                afr[i][1] = smu[G13_A(sl, r + grp + 8, s * 8 + tig)];
                afr[i][2] = smu[G13_A(sl, r + grp,     s * 8 + tig + 4)];
                afr[i][3] = smu[G13_A(sl, r + grp + 8, s * 8 + tig + 4)];
            }
            #pragma unroll
            for (int j = 0; j < 4; j++) {
                int nn = wn * 32 + j * 8 + grp;
                uint32_t b10 = smu[G13_B1(sl, s * 8 + tig,     nn)];
                uint32_t b11 = smu[G13_B1(sl, s * 8 + tig + 4, nn)];
                MMA_TF32(accH[0][j], afr[0], b10, b11);
                MMA_TF32(accH[1][j], afr[1], b10, b11);
                uint32_t b30 = smu[G13_B3(sl, s * 8 + tig,     nn)];
                uint32_t b31 = smu[G13_B3(sl, s * 8 + tig + 4, nn)];
                MMA_TF32(accG[0][j], afr[0], b30, b31);
                MMA_TF32(accG[1][j], afr[1], b30, b31);
            }
        }
    }

    // epilogue: silu(h)*g, rounded to tf32 so gemm2 can consume raw bits
    #pragma unroll
    for (int i = 0; i < 2; i++) {
        int r0 = m0 + wm * 32 + i * 16 + grp;
        #pragma unroll
        for (int j = 0; j < 4; j++) {
            int cb = n0 + wn * 32 + j * 8 + tig * 2;
            if (r0 < cnt) {
                float2 v;
                v.x = __uint_as_float(f2tf(silu_mul(accH[i][j][0], accG[i][j][0])));
                v.y = __uint_as_float(f2tf(silu_mul(accH[i][j][1], accG[i][j][1])));
                *(float2*)(g_abuf + (size_t)(off + r0) * HH + cb) = v;
            }
            if (r0 + 8 < cnt) {
                float2 v;
                v.x = __uint_as_float(f2tf(silu_mul(accH[i][j][2], accG[i][j][2])));
                v.y = __uint_as_float(f2tf(silu_mul(accH[i][j][3], accG[i][j][3])));
                *(float2*)(g_abuf + (size_t)(off + r0 + 8) * HH + cb) = v;
            }
        }
    }
}

// ---------------- gemm2 fills ------------------------------------------------------
__device__ __forceinline__ void fill2(uint32_t sbase, int st, int c, int tid,
                                      int arow0, const float* wB, int n0) {
    int k0 = c * 32;
    #pragma unroll
    for (int f = 0; f < 4; f++) {
        int id = tid + 256 * f;
        int m = id >> 3, k4 = (id & 7) * 4;
        cp16(sbase + G2_A(st, m, k4) * 4, g_abuf + (size_t)(arow0 + m) * HH + k0 + k4);
    }
    #pragma unroll
    for (int f = 0; f < 2; f++) {
        int id = tid + 256 * f;
        int k = id >> 4, n4 = (id & 15) * 4;
        cp16(sbase + G2_B(st, k, n4) * 4, wB + (size_t)(k0 + k) * DD + n0 + n4);
    }
}

// ---------------- GEMM2: ybuf = abuf @ W2  (3-stage cp.async) ----------------------
__global__ __launch_bounds__(256, 2)
void gemm2_tc() {
    int e   = blockIdx.z;
    int cnt = g_counts[e];
    int m0  = blockIdx.y * 128;
    if (m0 >= cnt) return;
    int off = g_offsets[e];
    int n0  = blockIdx.x * 64;
    const float* wB = g_w2r + (size_t)e * NWE;

    // clamp A source block so reads stay in-bounds (tail rows read junk; stores guarded)
    int arow0 = off + m0;
    if (arow0 > TKS - 128) arow0 = TKS - 128;

    extern __shared__ float sm[];
    uint32_t* smu = (uint32_t*)sm;
    uint32_t sbase = smem_u32(sm);

    int tid = threadIdx.x;
    int wid = tid >> 5, lane = tid & 31;
    int grp = lane >> 2, tig = lane & 3;
    int wm = wid & 3, wn = wid >> 2;

    float acc[2][4][4];
    #pragma unroll
    for (int i = 0; i < 2; i++)
        #pragma unroll
        for (int j = 0; j < 4; j++)
            #pragma unroll
            for (int q = 0; q < 4; q++) acc[i][j][q] = 0.0f;

    fill2(sbase, 0, 0, tid, arow0, wB, n0); cp_commit();
    fill2(sbase, 1, 1, tid, arow0, wB, n0); cp_commit();

    for (int c = 0; c < HH / 32; c++) {
        cp_wait<1>();
        __syncthreads();
        if (c + 2 < HH / 32)
            fill2(sbase, (c + 2) % 3, c + 2, tid, arow0, wB, n0);
        cp_commit();

        int sl = c % 3;
        #pragma unroll
        for (int s = 0; s < 4; s++) {
            uint32_t afr[2][4];
            #pragma unroll
            for (int i = 0; i < 2; i++) {
                int r = wm * 32 + i * 16;
                afr[i][0] = smu[G2_A(sl, r + grp,     s * 8 + tig)];
                afr[i][1] = smu[G2_A(sl, r + grp + 8, s * 8 + tig)];
                afr[i][2] = smu[G2_A(sl, r + grp,     s * 8 + tig + 4)];
                afr[i][3] = smu[G2_A(sl, r + grp + 8, s * 8 + tig + 4)];
            }
            #pragma unroll
            for (int j = 0; j < 4; j++) {
                int nn = wn * 32 + j * 8 + grp;
                uint32_t b0 = smu[G2_B(sl, s * 8 + tig,     nn)];
                uint32_t b1 = smu[G2_B(sl, s * 8 + tig + 4, nn)];
                MMA_TF32(acc[0][j], afr[0], b0, b1);
                MMA_TF32(acc[1][j], afr[1], b0, b1);
            }
        }
    }

    int adj = (off + m0) - arow0;   // shift if A block was clamped
    #pragma unroll
    for (int i = 0; i < 2; i++) {
        int rr = wm * 32 + i * 16 + grp - adj;   // row within logical tile
        int r0 = m0 + rr;
        #pragma unroll
        for (int j = 0; j < 4; j++) {
            int cb = n0 + wn * 32 + j * 8 + tig * 2;
            if (rr >= 0 && r0 < cnt)
                *(float2*)(g_ybuf + (size_t)(off + r0) * DD + cb) = make_float2(acc[i][j][0], acc[i][j][1]);
            if (rr + 8 >= 0 && r0 + 8 < cnt)
                *(float2*)(g_ybuf + (size_t)(off + r0 + 8) * DD + cb) = make_float2(acc[i][j][2], acc[i][j][3]);
        }
    }
}

// ---------------- combine ------------------------------------------------------
__global__ void combine_kernel(float* __restrict__ out) {
    int id = blockIdx.x * blockDim.x + threadIdx.x;
    int t  = id >> 8;
    int d4 = (id & 255) * 4;
    float4 acc = make_float4(0.f, 0.f, 0.f, 0.f);
    #pragma unroll
    for (int k = 0; k < KK; k++) {
        int   slot = g_slot[t * KK + k];
        float w    = g_topk_w[t * KK + k];
        float4 v = *(const float4*)(g_ybuf + (size_t)slot * DD + d4);
        acc.x += w * v.x; acc.y += w * v.y; acc.z += w * v.z; acc.w += w * v.w;
    }
    *(float4*)(out + (size_t)t * DD + d4) = acc;
}

// ---------------- launch ---------------------------------------------------------
extern "C" void kernel_launch(void* const* d_in, const int* in_sizes, int n_in,
                              void* d_out, int out_size) {
    const float* x    = (const float*)d_in[0];
    const float* gw   = (const float*)d_in[1];
    const float* bias = (const float*)d_in[2];
    const float* w1   = (const float*)d_in[3];
    const float* w3   = (const float*)d_in[4];
    const float* w2   = (const float*)d_in[5];
    float* out = (float*)d_out;

    cudaFuncSetAttribute(gemm13_tc, cudaFuncAttributeMaxDynamicSharedMemorySize, SMEM13);
    cudaFuncSetAttribute(gemm2_tc,  cudaFuncAttributeMaxDynamicSharedMemorySize, SMEM2);

    convert_kernel<<<4096, 256>>>(w1, w3, w2, x);

    int tail = out_size - TT * DD;
    int nb = (tail + EE + 255) / 256; if (nb < 1) nb = 1;
    init_kernel<<<nb, 256>>>(out, out_size);
    router_kernel<<<TT, 128>>>(x, gw, bias);
    scan_kernel<<<1, 32>>>(out, out_size);
    scatter_kernel<<<TKS / 256, 256>>>();

    dim3 g1(HH / 64, TT / 128, EE);   // (16, 16, 16)
    gemm13_tc<<<g1, 256, SMEM13>>>();

    dim3 g2(DD / 64, TT / 128, EE);   // (16, 16, 16)
    gemm2_tc<<<g2, 256, SMEM2>>>();

    combine_kernel<<<(TT * DD / 4) / 256, 256>>>(out);
}

// round 6
// speedup vs baseline: 4.1728x; 1.3436x over previous
#include <cuda_runtime.h>
#include <cuda_fp16.h>
#include <math.h>
#include <stdint.h>

#define TT   2048
#define DD   1024
#define EE   16
#define HH   1024
#define KK   4
#define TKS  (TT*KK)
#define NWE  (DD*HH)
#define EPSF 1e-6f

// ---------------- device scratch (static; no cudaMalloc) --------------------
__device__ float  g_ssum[EE];
__device__ int    g_counts[EE];
__device__ int    g_offsets[EE];
__device__ int    g_fill[EE];
__device__ int    g_tok[TKS];
__device__ int    g_slot[TKS];
__device__ int    g_topk_e[TKS];
__device__ float  g_topk_w[TKS];
__device__ __half g_xh [(size_t)TT * DD];       // x in fp16
__device__ __half g_w1t[(size_t)EE * NWE];      // w1^T per expert: [H][D] fp16
__device__ __half g_w3t[(size_t)EE * NWE];      // w3^T: [H][D]
__device__ __half g_w2t[(size_t)EE * NWE];      // w2^T: [D][H]
__device__ __half g_abuf[(size_t)TKS * HH];     // silu(x@w1)*(x@w3) fp16
__device__ float  g_ybuf[(size_t)TKS * DD];

// ---------------- helpers ------------------------------------------------------
#define MMA_F16(c, a, b0, b1) \
  asm volatile("mma.sync.aligned.m16n8k16.row.col.f32.f16.f16.f32 " \
    "{%0,%1,%2,%3}, {%4,%5,%6,%7}, {%8,%9}, {%0,%1,%2,%3};" \
    : "+f"((c)[0]), "+f"((c)[1]), "+f"((c)[2]), "+f"((c)[3]) \
    : "r"((a)[0]), "r"((a)[1]), "r"((a)[2]), "r"((a)[3]), "r"(b0), "r"(b1))

__device__ __forceinline__ float silu_mul(float h, float g) {
    return (h / (1.0f + expf(-h))) * g;
}
__device__ __forceinline__ uint32_t smem_u32(const void* p) {
    uint32_t r;
    asm("{ .reg .u64 t; cvta.to.shared.u64 t, %1; cvt.u32.u64 %0, t; }" : "=r"(r) : "l"(p));
    return r;
}
__device__ __forceinline__ void cp16(uint32_t d, const void* s) {
    asm volatile("cp.async.cg.shared.global [%0], [%1], 16;" :: "r"(d), "l"(s));
}
__device__ __forceinline__ void cp_commit() { asm volatile("cp.async.commit_group;" ::: "memory"); }
template<int N>
__device__ __forceinline__ void cp_wait() { asm volatile("cp.async.wait_group %0;" :: "n"(N) : "memory"); }

// SMEM layouts in HALVES. Row pitch 40 halves (80B): bank-conflict-free fragments.
// gemm13 stage = A[128][40] + B1[64][40] + B3[64][40] = 10240 halves (20480B), 3 stages.
#define H13_A(s,m)   ((s)*10240 + (m)*40)
#define H13_B1(s,n)  ((s)*10240 + 5120 + (n)*40)
#define H13_B3(s,n)  ((s)*10240 + 7680 + (n)*40)
#define SMEM13 (3 * 20480)
// gemm2 stage = A[128][40] + B[64][40] = 7680 halves (15360B), 3 stages.
#define H2_A(s,m)    ((s)*7680 + (m)*40)
#define H2_B(s,n)    ((s)*7680 + 5120 + (n)*40)
#define SMEM2  (3 * 15360)

// ---------------- transpose+convert: w -> fp16 transposed -----------------------
// src [e][R=1024][C=1024] fp32 -> dst [e][C][R] fp16
__global__ void transpose_cvt_kernel(const float* __restrict__ w1,
                                     const float* __restrict__ w3,
                                     const float* __restrict__ w2) {
    __shared__ float t[32][33];
    int which = blockIdx.z >> 4, e = blockIdx.z & 15;
    const float* src;
    __half* dst;
    if (which == 0)      { src = w1; dst = g_w1t; }
    else if (which == 1) { src = w3; dst = g_w3t; }
    else                 { src = w2; dst = g_w2t; }
    src += (size_t)e * NWE;
    dst += (size_t)e * NWE;
    int c0 = blockIdx.x * 32, r0 = blockIdx.y * 32;
    int tx = threadIdx.x, ty = threadIdx.y;
    #pragma unroll
    for (int u = 0; u < 4; u++)
        t[ty + 8 * u][tx] = src[(size_t)(r0 + ty + 8 * u) * 1024 + c0 + tx];
    __syncthreads();
    #pragma unroll
    for (int u = 0; u < 4; u++)
        dst[(size_t)(c0 + ty + 8 * u) * 1024 + r0 + tx] = __float2half_rn(t[tx][ty + 8 * u]);
}

// ---------------- x -> fp16 ------------------------------------------------------
__global__ void xcvt_kernel(const float* __restrict__ x) {
    int i = blockIdx.x * 256 + threadIdx.x;   // TT*DD/4 threads
    float4 v = ((const float4*)x)[i];
    ((__half2*)g_xh)[2 * i]     = __floats2half2_rn(v.x, v.y);
    ((__half2*)g_xh)[2 * i + 1] = __floats2half2_rn(v.z, v.w);
}

// ---------------- init ----------------------------------------------------------
__global__ void init_kernel(float* __restrict__ out, int out_size) {
    int i = blockIdx.x * blockDim.x + threadIdx.x;
    if (i < EE) { g_counts[i] = 0; g_ssum[i] = 0.0f; g_fill[i] = 0; }
    int t = TT * DD + i;
    if (t < out_size) out[t] = 0.0f;
}

// ---------------- router (exact fp32) -------------------------------------------
__global__ void router_kernel(const float* __restrict__ x,
                              const float* __restrict__ gw,
                              const float* __restrict__ bias) {
    int t = blockIdx.x;
    __shared__ float xs[DD];
    __shared__ float logits[EE];
    __shared__ float scores[EE];
    int tid = threadIdx.x;
    for (int d = tid; d < DD; d += 128) xs[d] = x[t * DD + d];
    __syncthreads();

    int warp = tid >> 5, lane = tid & 31;
    for (int e = warp; e < EE; e += 4) {
        float s = 0.0f;
        for (int d = lane; d < DD; d += 32) s += xs[d] * gw[d * EE + e];
        #pragma unroll
        for (int o = 16; o; o >>= 1) s += __shfl_down_sync(0xffffffff, s, o);
        if (lane == 0) logits[e] = s + bias[e];
    }
    __syncthreads();

    if (tid == 0) {
        float ssum = 0.0f;
        #pragma unroll
        for (int e = 0; e < EE; e++) {
            float sc = 1.0f / (1.0f + expf(-logits[e]));
            scores[e] = sc; ssum += sc;
        }
        float inv = 1.0f / (ssum + EPSF);
        #pragma unroll
        for (int e = 0; e < EE; e++) {
            scores[e] *= inv;
            atomicAdd(&g_ssum[e], scores[e]);
        }
        unsigned used = 0u;
        int idx[KK]; float val[KK]; float wsum = 0.0f;
        #pragma unroll
        for (int k = 0; k < KK; k++) {
            float best = -1e30f; int bi = 0;
            #pragma unroll
            for (int e = 0; e < EE; e++)
                if (!((used >> e) & 1u) && scores[e] > best) { best = scores[e]; bi = e; }
            used |= (1u << bi);
            idx[k] = bi; val[k] = best; wsum += best;
        }
        float winv = 1.0f / (wsum + EPSF);
        #pragma unroll
        for (int k = 0; k < KK; k++) {
            g_topk_e[t * KK + k] = idx[k];
            g_topk_w[t * KK + k] = val[k] * winv;
            atomicAdd(&g_counts[idx[k]], 1);
        }
    }
}

// ---------------- scan + lb loss -------------------------------------------------
__global__ void scan_kernel(float* __restrict__ out, int out_size) {
    if (threadIdx.x == 0 && blockIdx.x == 0) {
        int off = 0;
        #pragma unroll
        for (int e = 0; e < EE; e++) { g_offsets[e] = off; off += g_counts[e]; }
        float lb = 0.0f;
        #pragma unroll
        for (int e = 0; e < EE; e++) lb += (float)g_counts[e] * g_ssum[e];
        lb *= (float)EE / ((float)TT * (float)TT);
        if (out_size > TT * DD) out[TT * DD] = lb;
    }
}

// ---------------- scatter --------------------------------------------------------
__global__ void scatter_kernel() {
    int i = blockIdx.x * blockDim.x + threadIdx.x;
    if (i >= TKS) return;
    int t = i >> 2;
    int e = g_topk_e[i];
    int pos = atomicAdd(&g_fill[e], 1);
    int slot = g_offsets[e] + pos;
    g_tok[slot] = t;
    g_slot[i]   = slot;
}

// ---------------- gemm13 fill (fp16 cp.async) -------------------------------------
__device__ __forceinline__ void fill13(uint32_t sbase, int st, int c, int tid,
                                       const int* rowb, const __half* w1e,
                                       const __half* w3e, int n0) {
    int k0 = c * 32;
    #pragma unroll
    for (int f = 0; f < 2; f++) {
        int id = tid + 256 * f;
        int m = id >> 2, q = (id & 3) * 8;
        cp16(sbase + (H13_A(st, m) + q) * 2, g_xh + rowb[m] + k0 + q);
    }
    {
        int n = tid >> 2, q = (tid & 3) * 8;
        size_t gofs = (size_t)(n0 + n) * DD + k0 + q;
        cp16(sbase + (H13_B1(st, n) + q) * 2, w1e + gofs);
        cp16(sbase + (H13_B3(st, n) + q) * 2, w3e + gofs);
    }
}

// ---------------- GEMM13: abuf = silu(gather(x)@W1) * (gather(x)@W3) ---------------
// CTA 128(M) x 64(N), KT=32, 3-stage cp.async, 8 warps (4m x 2n), warp 32x32.
__global__ __launch_bounds__(256, 2)
void gemm13_tc() {
    int e   = blockIdx.z;
    int cnt = g_counts[e];
    int m0  = blockIdx.y * 128;
    if (m0 >= cnt) return;
    int off = g_offsets[e];
    int n0  = blockIdx.x * 64;
    const __half* w1e = g_w1t + (size_t)e * NWE;
    const __half* w3e = g_w3t + (size_t)e * NWE;

    extern __shared__ __half sh[];
    uint32_t* smu = (uint32_t*)sh;
    uint32_t sbase = smem_u32(sh);
    __shared__ int rowb[128];

    int tid = threadIdx.x;
    if (tid < 128) {
        int m = m0 + tid;
        rowb[tid] = g_tok[off + (m < cnt ? m : cnt - 1)] * DD;
    }
    __syncthreads();

    int wid = tid >> 5, lane = tid & 31;
    int grp = lane >> 2, tig = lane & 3;
    int wm = wid & 3, wn = wid >> 2;

    float accH[2][4][4], accG[2][4][4];
    #pragma unroll
    for (int i = 0; i < 2; i++)
        #pragma unroll
        for (int j = 0; j < 4; j++)
            #pragma unroll
            for (int q = 0; q < 4; q++) { accH[i][j][q] = 0.0f; accG[i][j][q] = 0.0f; }

    fill13(sbase, 0, 0, tid, rowb, w1e, w3e, n0); cp_commit();
    fill13(sbase, 1, 1, tid, rowb, w1e, w3e, n0); cp_commit();

    for (int c = 0; c < DD / 32; c++) {
        cp_wait<1>();
        __syncthreads();
        if (c + 2 < DD / 32)
            fill13(sbase, (c + 2) % 3, c + 2, tid, rowb, w1e, w3e, n0);
        cp_commit();

        int sl = c % 3;
        int abase0 = sl * 5120;                      // u32 index of stage A
        int bbase1 = sl * 5120 + 2560;               // u32 index of stage B1
        int bbase3 = sl * 5120 + 3840;               // u32 index of stage B3
        #pragma unroll
        for (int s = 0; s < 2; s++) {
            uint32_t afr[2][4];
            #pragma unroll
            for (int i = 0; i < 2; i++) {
                int base = abase0 + (wm * 32 + i * 16 + grp) * 20 + s * 8 + tig;
                afr[i][0] = smu[base];
                afr[i][1] = smu[base + 160];
                afr[i][2] = smu[base + 4];
                afr[i][3] = smu[base + 164];
            }
            #pragma unroll
            for (int j = 0; j < 4; j++) {
                int nw = (wn * 32 + j * 8 + grp) * 20 + s * 8 + tig;
                uint32_t b10 = smu[bbase1 + nw], b11 = smu[bbase1 + nw + 4];
                MMA_F16(accH[0][j], afr[0], b10, b11);
                MMA_F16(accH[1][j], afr[1], b10, b11);
                uint32_t b30 = smu[bbase3 + nw], b31 = smu[bbase3 + nw + 4];
                MMA_F16(accG[0][j], afr[0], b30, b31);
                MMA_F16(accG[1][j], afr[1], b30, b31);
            }
        }
    }

    // epilogue: silu(h)*g -> fp16 abuf (n-pairs == gemm2's k-pairs)
    #pragma unroll
    for (int i = 0; i < 2; i++) {
        int r0 = m0 + wm * 32 + i * 16 + grp;
        #pragma unroll
        for (int j = 0; j < 4; j++) {
            int cb = n0 + wn * 32 + j * 8 + tig * 2;
            if (r0 < cnt) {
                *(__half2*)(g_abuf + (size_t)(off + r0) * HH + cb) =
                    __floats2half2_rn(silu_mul(accH[i][j][0], accG[i][j][0]),
                                      silu_mul(accH[i][j][1], accG[i][j][1]));
            }
            if (r0 + 8 < cnt) {
                *(__half2*)(g_abuf + (size_t)(off + r0 + 8) * HH + cb) =
                    __floats2half2_rn(silu_mul(accH[i][j][2], accG[i][j][2]),
                                      silu_mul(accH[i][j][3], accG[i][j][3]));
            }
        }
    }
}

// ---------------- gemm2 fill --------------------------------------------------------
__device__ __forceinline__ void fill2(uint32_t sbase, int st, int c, int tid,
                                      int arow0, const __half* wB, int n0) {
    int k0 = c * 32;
    #pragma unroll
    for (int f = 0; f < 2; f++) {
        int id = tid + 256 * f;
        int m = id >> 2, q = (id & 3) * 8;
        cp16(sbase + (H2_A(st, m) + q) * 2, g_abuf + (size_t)(arow0 + m) * HH + k0 + q);
    }
    {
        int n = tid >> 2, q = (tid & 3) * 8;
        cp16(sbase + (H2_B(st, n) + q) * 2, wB + (size_t)(n0 + n) * HH + k0 + q);
    }
}

// ---------------- GEMM2: ybuf = abuf @ W2 -------------------------------------------
__global__ __launch_bounds__(256, 2)
void gemm2_tc() {
    int e   = blockIdx.z;
    int cnt = g_counts[e];
    int m0  = blockIdx.y * 128;
    if (m0 >= cnt) return;
    int off = g_offsets[e];
    int n0  = blockIdx.x * 64;
    const __half* wB = g_w2t + (size_t)e * NWE;

    int arow0 = off + m0;
    if (arow0 > TKS - 128) arow0 = TKS - 128;

    extern __shared__ __half sh[];
    uint32_t* smu = (uint32_t*)sh;
    uint32_t sbase = smem_u32(sh);

    int tid = threadIdx.x;
    int wid = tid >> 5, lane = tid & 31;
    int grp = lane >> 2, tig = lane & 3;
    int wm = wid & 3, wn = wid >> 2;

    float acc[2][4][4];
    #pragma unroll
    for (int i = 0; i < 2; i++)
        #pragma unroll
        for (int j = 0; j < 4; j++)
            #pragma unroll
            for (int q = 0; q < 4; q++) acc[i][j][q] = 0.0f;

    fill2(sbase, 0, 0, tid, arow0, wB, n0); cp_commit();
    fill2(sbase, 1, 1, tid, arow0, wB, n0); cp_commit();

    for (int c = 0; c < HH / 32; c++) {
        cp_wait<1>();
        __syncthreads();
        if (c + 2 < HH / 32)
            fill2(sbase, (c + 2) % 3, c + 2, tid, arow0, wB, n0);
        cp_commit();

        int sl = c % 3;
        int abase0 = sl * 3840;
        int bbase  = sl * 3840 + 2560;
        #pragma unroll
        for (int s = 0; s < 2; s++) {
            uint32_t afr[2][4];
            #pragma unroll
            for (int i = 0; i < 2; i++) {
                int base = abase0 + (wm * 32 + i * 16 + grp) * 20 + s * 8 + tig;
                afr[i][0] = smu[base];
                afr[i][1] = smu[base + 160];
                afr[i][2] = smu[base + 4];
                afr[i][3] = smu[base + 164];
            }
            #pragma unroll
            for (int j = 0; j < 4; j++) {
                int nw = (wn * 32 + j * 8 + grp) * 20 + s * 8 + tig;
                uint32_t b0 = smu[bbase + nw], b1 = smu[bbase + nw + 4];
                MMA_F16(acc[0][j], afr[0], b0, b1);
                MMA_F16(acc[1][j], afr[1], b0, b1);
            }
        }
    }

    int adj = (off + m0) - arow0;
    #pragma unroll
    for (int i = 0; i < 2; i++) {
        int rr = wm * 32 + i * 16 + grp - adj;
        int r0 = m0 + rr;
        #pragma unroll
        for (int j = 0; j < 4; j++) {
            int cb = n0 + wn * 32 + j * 8 + tig * 2;
            if (rr >= 0 && r0 < cnt)
                *(float2*)(g_ybuf + (size_t)(off + r0) * DD + cb) = make_float2(acc[i][j][0], acc[i][j][1]);
            if (rr + 8 >= 0 && r0 + 8 < cnt)
                *(float2*)(g_ybuf + (size_t)(off + r0 + 8) * DD + cb) = make_float2(acc[i][j][2], acc[i][j][3]);
        }
    }
}

// ---------------- combine ------------------------------------------------------
__global__ void combine_kernel(float* __restrict__ out) {
    int id = blockIdx.x * blockDim.x + threadIdx.x;
    int t  = id >> 8;
    int d4 = (id & 255) * 4;
    float4 acc = make_float4(0.f, 0.f, 0.f, 0.f);
    #pragma unroll
    for (int k = 0; k < KK; k++) {
        int   slot = g_slot[t * KK + k];
        float w    = g_topk_w[t * KK + k];
        float4 v = *(const float4*)(g_ybuf + (size_t)slot * DD + d4);
        acc.x += w * v.x; acc.y += w * v.y; acc.z += w * v.z; acc.w += w * v.w;
    }
    *(float4*)(out + (size_t)t * DD + d4) = acc;
}

// ---------------- launch ---------------------------------------------------------
extern "C" void kernel_launch(void* const* d_in, const int* in_sizes, int n_in,
                              void* d_out, int out_size) {
    const float* x    = (const float*)d_in[0];
    const float* gw   = (const float*)d_in[1];
    const float* bias = (const float*)d_in[2];
    const float* w1   = (const float*)d_in[3];
    const float* w3   = (const float*)d_in[4];
    const float* w2   = (const float*)d_in[5];
    float* out = (float*)d_out;

    cudaFuncSetAttribute(gemm13_tc, cudaFuncAttributeMaxDynamicSharedMemorySize, SMEM13);
    cudaFuncSetAttribute(gemm2_tc,  cudaFuncAttributeMaxDynamicSharedMemorySize, SMEM2);

    dim3 tg(32, 32, 48);
    transpose_cvt_kernel<<<tg, dim3(32, 8)>>>(w1, w3, w2);
    xcvt_kernel<<<(TT * DD / 4) / 256, 256>>>(x);

    int tail = out_size - TT * DD;
    int nb = (tail + EE + 255) / 256; if (nb < 1) nb = 1;
    init_kernel<<<nb, 256>>>(out, out_size);
    router_kernel<<<TT, 128>>>(x, gw, bias);
    scan_kernel<<<1, 32>>>(out, out_size);
    scatter_kernel<<<TKS / 256, 256>>>();

    dim3 g1(HH / 64, TT / 128, EE);   // (16, 16, 16)
    gemm13_tc<<<g1, 256, SMEM13>>>();

    dim3 g2(DD / 64, TT / 128, EE);   // (16, 16, 16)
    gemm2_tc<<<g2, 256, SMEM2>>>();

    combine_kernel<<<(TT * DD / 4) / 256, 256>>>(out);
}

// round 7
// speedup vs baseline: 4.9847x; 1.1946x over previous
#include <cuda_runtime.h>
#include <cuda_fp16.h>
#include <math.h>
#include <stdint.h>

#define TT   2048
#define DD   1024
#define EE   16
#define HH   1024
#define KK   4
#define TKS  (TT*KK)
#define NWE  (DD*HH)
#define EPSF 1e-6f

// ---------------- device scratch (static; no cudaMalloc) --------------------
__device__ float  g_ssum[EE];
__device__ int    g_counts[EE];
__device__ int    g_offsets[EE];
__device__ int    g_fill[EE];
__device__ int    g_tok[TKS];
__device__ int    g_slot[TKS];
__device__ int    g_topk_e[TKS];
__device__ float  g_topk_w[TKS];
__device__ __half g_xh [(size_t)TT * DD];
__device__ __half g_w1t[(size_t)EE * NWE];      // w1^T per expert: [H][D] fp16
__device__ __half g_w3t[(size_t)EE * NWE];
__device__ __half g_w2t[(size_t)EE * NWE];      // w2^T: [D][H]
__device__ __half g_abuf[(size_t)TKS * HH];
__device__ float  g_ybuf[(size_t)TKS * DD];

// ---------------- helpers ------------------------------------------------------
#define MMA_F16(c, a, b0, b1) \
  asm volatile("mma.sync.aligned.m16n8k16.row.col.f32.f16.f16.f32 " \
    "{%0,%1,%2,%3}, {%4,%5,%6,%7}, {%8,%9}, {%0,%1,%2,%3};" \
    : "+f"((c)[0]), "+f"((c)[1]), "+f"((c)[2]), "+f"((c)[3]) \
    : "r"((a)[0]), "r"((a)[1]), "r"((a)[2]), "r"((a)[3]), "r"(b0), "r"(b1))

__device__ __forceinline__ float silu_mul(float h, float g) {
    return (h / (1.0f + expf(-h))) * g;
}
__device__ __forceinline__ uint32_t smem_u32(const void* p) {
    uint32_t r;
    asm("{ .reg .u64 t; cvta.to.shared.u64 t, %1; cvt.u32.u64 %0, t; }" : "=r"(r) : "l"(p));
    return r;
}
__device__ __forceinline__ void cp16(uint32_t d, const void* s) {
    asm volatile("cp.async.cg.shared.global [%0], [%1], 16;" :: "r"(d), "l"(s));
}
__device__ __forceinline__ void cp_commit() { asm volatile("cp.async.commit_group;" ::: "memory"); }
template<int N>
__device__ __forceinline__ void cp_wait() { asm volatile("cp.async.wait_group %0;" :: "n"(N) : "memory"); }

// SMEM layouts in HALVES, pitch 40 (conflict-free fragments).
// gemm13 stage = A[128][40] + B1[64][40] + B3[64][40] = 10240 halves, 3 stages.
#define H13_A(s,m)   ((s)*10240 + (m)*40)
#define H13_B1(s,n)  ((s)*10240 + 5120 + (n)*40)
#define H13_B3(s,n)  ((s)*10240 + 7680 + (n)*40)
#define SMEM13 (3 * 20480)
// gemm2 stage = A[128][40] + B[128][40] = 10240 halves, 3 stages.
#define H2_A(s,m)    ((s)*10240 + (m)*40)
#define H2_B(s,n)    ((s)*10240 + 5120 + (n)*40)
#define SMEM2  (3 * 20480)

// ---------------- transpose+convert: w -> fp16 transposed -----------------------
__global__ void transpose_cvt_kernel(const float* __restrict__ w1,
                                     const float* __restrict__ w3,
                                     const float* __restrict__ w2) {
    __shared__ float t[32][33];
    int which = blockIdx.z >> 4, e = blockIdx.z & 15;
    const float* src;
    __half* dst;
    if (which == 0)      { src = w1; dst = g_w1t; }
    else if (which == 1) { src = w3; dst = g_w3t; }
    else                 { src = w2; dst = g_w2t; }
    src += (size_t)e * NWE;
    dst += (size_t)e * NWE;
    int c0 = blockIdx.x * 32, r0 = blockIdx.y * 32;
    int tx = threadIdx.x, ty = threadIdx.y;
    #pragma unroll
    for (int u = 0; u < 4; u++)
        t[ty + 8 * u][tx] = src[(size_t)(r0 + ty + 8 * u) * 1024 + c0 + tx];
    __syncthreads();
    #pragma unroll
    for (int u = 0; u < 4; u++)
        dst[(size_t)(c0 + ty + 8 * u) * 1024 + r0 + tx] = __float2half_rn(t[tx][ty + 8 * u]);
}

// ---------------- init ----------------------------------------------------------
__global__ void init_kernel(float* __restrict__ out, int out_size) {
    int i = blockIdx.x * blockDim.x + threadIdx.x;
    if (i < EE) { g_counts[i] = 0; g_ssum[i] = 0.0f; g_fill[i] = 0; }
    int t = TT * DD + i;
    if (t < out_size) out[t] = 0.0f;
}

// ---------------- router v2: block-staged gate_w, warp-per-token ----------------
// 128 blocks x 256 threads; 16 tokens/block (2 per warp). Fuses x->fp16 convert.
__global__ void router_kernel(const float* __restrict__ x,
                              const float* __restrict__ gw,
                              const float* __restrict__ bias) {
    extern __shared__ float gws[];             // [EE][DD] transposed, 64KB
    __shared__ float bssum[EE];
    int tid = threadIdx.x;
    if (tid < EE) bssum[tid] = 0.0f;
    for (int i = tid; i < DD * EE; i += 256) {
        int d = i >> 4, e = i & 15;            // gw is [D][E]
        gws[e * DD + d] = gw[i];
    }
    __syncthreads();

    int warp = tid >> 5, lane = tid & 31;
    #pragma unroll
    for (int tt = 0; tt < 2; tt++) {
        int t = blockIdx.x * 16 + warp * 2 + tt;
        float acc[EE];
        #pragma unroll
        for (int e = 0; e < EE; e++) acc[e] = 0.0f;
        for (int i = 0; i < DD / 32; i++) {
            int d = i * 32 + lane;
            float xv = x[(size_t)t * DD + d];
            g_xh[(size_t)t * DD + d] = __float2half_rn(xv);   // fused convert
            #pragma unroll
            for (int e = 0; e < EE; e++) acc[e] += xv * gws[e * DD + d];
        }
        #pragma unroll
        for (int o = 16; o; o >>= 1) {
            #pragma unroll
            for (int e = 0; e < EE; e++)
                acc[e] += __shfl_xor_sync(0xffffffff, acc[e], o);
        }
        if (lane == 0) {
            float sc[EE];
            float ssum = 0.0f;
            #pragma unroll
            for (int e = 0; e < EE; e++) {
                sc[e] = 1.0f / (1.0f + expf(-(acc[e] + bias[e])));
                ssum += sc[e];
            }
            float inv = 1.0f / (ssum + EPSF);
            #pragma unroll
            for (int e = 0; e < EE; e++) {
                sc[e] *= inv;
                atomicAdd(&bssum[e], sc[e]);
            }
            unsigned used = 0u;
            int idx[KK]; float val[KK]; float wsum = 0.0f;
            #pragma unroll
            for (int k = 0; k < KK; k++) {
                float best = -1e30f; int bi = 0;
                #pragma unroll
                for (int e = 0; e < EE; e++)
                    if (!((used >> e) & 1u) && sc[e] > best) { best = sc[e]; bi = e; }
                used |= (1u << bi);
                idx[k] = bi; val[k] = best; wsum += best;
            }
            float winv = 1.0f / (wsum + EPSF);
            #pragma unroll
            for (int k = 0; k < KK; k++) {
                g_topk_e[t * KK + k] = idx[k];
                g_topk_w[t * KK + k] = val[k] * winv;
                atomicAdd(&g_counts[idx[k]], 1);
            }
        }
    }
    __syncthreads();
    if (tid < EE) atomicAdd(&g_ssum[tid], bssum[tid]);
}

// ---------------- scan + lb loss -------------------------------------------------
__global__ void scan_kernel(float* __restrict__ out, int out_size) {
    if (threadIdx.x == 0 && blockIdx.x == 0) {
        int off = 0;
        #pragma unroll
        for (int e = 0; e < EE; e++) { g_offsets[e] = off; off += g_counts[e]; }
        float lb = 0.0f;
        #pragma unroll
        for (int e = 0; e < EE; e++) lb += (float)g_counts[e] * g_ssum[e];
        lb *= (float)EE / ((float)TT * (float)TT);
        if (out_size > TT * DD) out[TT * DD] = lb;
    }
}

// ---------------- scatter --------------------------------------------------------
__global__ void scatter_kernel() {
    int i = blockIdx.x * blockDim.x + threadIdx.x;
    if (i >= TKS) return;
    int t = i >> 2;
    int e = g_topk_e[i];
    int pos = atomicAdd(&g_fill[e], 1);
    int slot = g_offsets[e] + pos;
    g_tok[slot] = t;
    g_slot[i]   = slot;
}

// ---------------- gemm13 fill ------------------------------------------------------
__device__ __forceinline__ void fill13(uint32_t sbase, int st, int c, int tid,
                                       const int* rowb, const __half* w1e,
                                       const __half* w3e, int n0) {
    int k0 = c * 32;
    #pragma unroll
    for (int f = 0; f < 2; f++) {
        int id = tid + 256 * f;
        int m = id >> 2, q = (id & 3) * 8;
        cp16(sbase + (H13_A(st, m) + q) * 2, g_xh + rowb[m] + k0 + q);
    }
    {
        int n = tid >> 2, q = (tid & 3) * 8;
        size_t gofs = (size_t)(n0 + n) * DD + k0 + q;
        cp16(sbase + (H13_B1(st, n) + q) * 2, w1e + gofs);
        cp16(sbase + (H13_B3(st, n) + q) * 2, w3e + gofs);
    }
}

// ---------------- GEMM13: abuf = silu(gather(x)@W1) * (gather(x)@W3) ---------------
// CTA 128(M) x 64(N per mat), KT=32, 3-stage cp.async, 8 warps (4m x 2n), warp 32x32.
__global__ __launch_bounds__(256, 2)
void gemm13_tc() {
    int e   = blockIdx.z;
    int cnt = g_counts[e];
    int m0  = blockIdx.y * 128;
    if (m0 >= cnt) return;
    int off = g_offsets[e];
    int n0  = blockIdx.x * 64;
    const __half* w1e = g_w1t + (size_t)e * NWE;
    const __half* w3e = g_w3t + (size_t)e * NWE;

    extern __shared__ __half sh[];
    uint32_t* smu = (uint32_t*)sh;
    uint32_t sbase = smem_u32(sh);
    __shared__ int rowb[128];

    int tid = threadIdx.x;
    if (tid < 128) {
        int m = m0 + tid;
        rowb[tid] = g_tok[off + (m < cnt ? m : cnt - 1)] * DD;
    }
    __syncthreads();

    int wid = tid >> 5, lane = tid & 31;
    int grp = lane >> 2, tig = lane & 3;
    int wm = wid & 3, wn = wid >> 2;

    float accH[2][4][4], accG[2][4][4];
    #pragma unroll
    for (int i = 0; i < 2; i++)
        #pragma unroll
        for (int j = 0; j < 4; j++)
            #pragma unroll
            for (int q = 0; q < 4; q++) { accH[i][j][q] = 0.0f; accG[i][j][q] = 0.0f; }

    fill13(sbase, 0, 0, tid, rowb, w1e, w3e, n0); cp_commit();
    fill13(sbase, 1, 1, tid, rowb, w1e, w3e, n0); cp_commit();

    for (int c = 0; c < DD / 32; c++) {
        cp_wait<1>();
        __syncthreads();
        if (c + 2 < DD / 32)
            fill13(sbase, (c + 2) % 3, c + 2, tid, rowb, w1e, w3e, n0);
        cp_commit();

        int sl = c % 3;
        int abase0 = sl * 5120;
        int bbase1 = sl * 5120 + 2560;
        int bbase3 = sl * 5120 + 3840;
        #pragma unroll
        for (int s = 0; s < 2; s++) {
            uint32_t afr[2][4];
            #pragma unroll
            for (int i = 0; i < 2; i++) {
                int base = abase0 + (wm * 32 + i * 16 + grp) * 20 + s * 8 + tig;
                afr[i][0] = smu[base];
                afr[i][1] = smu[base + 160];
                afr[i][2] = smu[base + 4];
                afr[i][3] = smu[base + 164];
            }
            #pragma unroll
            for (int j = 0; j < 4; j++) {
                int nw = (wn * 32 + j * 8 + grp) * 20 + s * 8 + tig;
                uint32_t b10 = smu[bbase1 + nw], b11 = smu[bbase1 + nw + 4];
                MMA_F16(accH[0][j], afr[0], b10, b11);
                MMA_F16(accH[1][j], afr[1], b10, b11);
                uint32_t b30 = smu[bbase3 + nw], b31 = smu[bbase3 + nw + 4];
                MMA_F16(accG[0][j], afr[0], b30, b31);
                MMA_F16(accG[1][j], afr[1], b30, b31);
            }
        }
    }

    #pragma unroll
    for (int i = 0; i < 2; i++) {
        int r0 = m0 + wm * 32 + i * 16 + grp;
        #pragma unroll
        for (int j = 0; j < 4; j++) {
            int cb = n0 + wn * 32 + j * 8 + tig * 2;
            if (r0 < cnt) {
                *(__half2*)(g_abuf + (size_t)(off + r0) * HH + cb) =
                    __floats2half2_rn(silu_mul(accH[i][j][0], accG[i][j][0]),
                                      silu_mul(accH[i][j][1], accG[i][j][1]));
            }
            if (r0 + 8 < cnt) {
                *(__half2*)(g_abuf + (size_t)(off + r0 + 8) * HH + cb) =
                    __floats2half2_rn(silu_mul(accH[i][j][2], accG[i][j][2]),
                                      silu_mul(accH[i][j][3], accG[i][j][3]));
            }
        }
    }
}

// ---------------- gemm2 fill (N tile = 128) ----------------------------------------
__device__ __forceinline__ void fill2(uint32_t sbase, int st, int c, int tid,
                                      int arow0, const __half* wB, int n0) {
    int k0 = c * 32;
    #pragma unroll
    for (int f = 0; f < 2; f++) {
        int id = tid + 256 * f;
        int m = id >> 2, q = (id & 3) * 8;
        cp16(sbase + (H2_A(st, m) + q) * 2, g_abuf + (size_t)(arow0 + m) * HH + k0 + q);
    }
    #pragma unroll
    for (int f = 0; f < 2; f++) {
        int id = tid + 256 * f;
        int n = id >> 2, q = (id & 3) * 8;
        cp16(sbase + (H2_B(st, n) + q) * 2, wB + (size_t)(n0 + n) * HH + k0 + q);
    }
}

// ---------------- GEMM2: ybuf = abuf @ W2  (CTA 128x128, warp 64x32) ----------------
__global__ __launch_bounds__(256, 2)
void gemm2_tc() {
    int e   = blockIdx.z;
    int cnt = g_counts[e];
    int m0  = blockIdx.y * 128;
    if (m0 >= cnt) return;
    int off = g_offsets[e];
    int n0  = blockIdx.x * 128;
    const __half* wB = g_w2t + (size_t)e * NWE;

    int arow0 = off + m0;
    if (arow0 > TKS - 128) arow0 = TKS - 128;

    extern __shared__ __half sh[];
    uint32_t* smu = (uint32_t*)sh;
    uint32_t sbase = smem_u32(sh);

    int tid = threadIdx.x;
    int wid = tid >> 5, lane = tid & 31;
    int grp = lane >> 2, tig = lane & 3;
    int wm = wid & 1, wn = wid >> 1;          // 2m x 4n warps, warp tile 64x32

    float acc[4][4][4];
    #pragma unroll
    for (int i = 0; i < 4; i++)
        #pragma unroll
        for (int j = 0; j < 4; j++)
            #pragma unroll
            for (int q = 0; q < 4; q++) acc[i][j][q] = 0.0f;

    fill2(sbase, 0, 0, tid, arow0, wB, n0); cp_commit();
    fill2(sbase, 1, 1, tid, arow0, wB, n0); cp_commit();

    for (int c = 0; c < HH / 32; c++) {
        cp_wait<1>();
        __syncthreads();
        if (c + 2 < HH / 32)
            fill2(sbase, (c + 2) % 3, c + 2, tid, arow0, wB, n0);
        cp_commit();

        int sl = c % 3;
        int abase0 = sl * 5120;
        int bbase  = sl * 5120 + 2560;
        #pragma unroll
        for (int s = 0; s < 2; s++) {
            uint32_t afr[4][4];
            #pragma unroll
            for (int i = 0; i < 4; i++) {
                int base = abase0 + (wm * 64 + i * 16 + grp) * 20 + s * 8 + tig;
                afr[i][0] = smu[base];
                afr[i][1] = smu[base + 160];
                afr[i][2] = smu[base + 4];
                afr[i][3] = smu[base + 164];
            }
            #pragma unroll
            for (int j = 0; j < 4; j++) {
                int nw = (wn * 32 + j * 8 + grp) * 20 + s * 8 + tig;
                uint32_t b0 = smu[bbase + nw], b1 = smu[bbase + nw + 4];
                #pragma unroll
                for (int i = 0; i < 4; i++)
                    MMA_F16(acc[i][j], afr[i], b0, b1);
            }
        }
    }

    int adj = (off + m0) - arow0;
    #pragma unroll
    for (int i = 0; i < 4; i++) {
        int rr = wm * 64 + i * 16 + grp - adj;
        int r0 = m0 + rr;
        #pragma unroll
        for (int j = 0; j < 4; j++) {
            int cb = n0 + wn * 32 + j * 8 + tig * 2;
            if (rr >= 0 && r0 < cnt)
                *(float2*)(g_ybuf + (size_t)(off + r0) * DD + cb) = make_float2(acc[i][j][0], acc[i][j][1]);
            if (rr + 8 >= 0 && r0 + 8 < cnt)
                *(float2*)(g_ybuf + (size_t)(off + r0 + 8) * DD + cb) = make_float2(acc[i][j][2], acc[i][j][3]);
        }
    }
}

// ---------------- combine ------------------------------------------------------
__global__ void combine_kernel(float* __restrict__ out) {
    int id = blockIdx.x * blockDim.x + threadIdx.x;
    int t  = id >> 8;
    int d4 = (id & 255) * 4;
    float4 acc = make_float4(0.f, 0.f, 0.f, 0.f);
    #pragma unroll
    for (int k = 0; k < KK; k++) {
        int   slot = g_slot[t * KK + k];
        float w    = g_topk_w[t * KK + k];
        float4 v = *(const float4*)(g_ybuf + (size_t)slot * DD + d4);
        acc.x += w * v.x; acc.y += w * v.y; acc.z += w * v.z; acc.w += w * v.w;
    }
    *(float4*)(out + (size_t)t * DD + d4) = acc;
}

// ---------------- launch ---------------------------------------------------------
extern "C" void kernel_launch(void* const* d_in, const int* in_sizes, int n_in,
                              void* d_out, int out_size) {
    const float* x    = (const float*)d_in[0];
    const float* gw   = (const float*)d_in[1];
    const float* bias = (const float*)d_in[2];
    const float* w1   = (const float*)d_in[3];
    const float* w3   = (const float*)d_in[4];
    const float* w2   = (const float*)d_in[5];
    float* out = (float*)d_out;

    cudaFuncSetAttribute(gemm13_tc, cudaFuncAttributeMaxDynamicSharedMemorySize, SMEM13);
    cudaFuncSetAttribute(gemm2_tc,  cudaFuncAttributeMaxDynamicSharedMemorySize, SMEM2);
    cudaFuncSetAttribute(router_kernel, cudaFuncAttributeMaxDynamicSharedMemorySize, DD * EE * 4);

    dim3 tg(32, 32, 48);
    transpose_cvt_kernel<<<tg, dim3(32, 8)>>>(w1, w3, w2);

    int tail = out_size - TT * DD;
    int nb = (tail + EE + 255) / 256; if (nb < 1) nb = 1;
    init_kernel<<<nb, 256>>>(out, out_size);
    router_kernel<<<128, 256, DD * EE * 4>>>(x, gw, bias);
    scan_kernel<<<1, 32>>>(out, out_size);
    scatter_kernel<<<TKS / 256, 256>>>();

    dim3 g1(HH / 64, TT / 128, EE);    // (16, 16, 16)
    gemm13_tc<<<g1, 256, SMEM13>>>();

    dim3 g2(DD / 128, TT / 128, EE);   // (8, 16, 16)
    gemm2_tc<<<g2, 256, SMEM2>>>();

    combine_kernel<<<(TT * DD / 4) / 256, 256>>>(out);
}

// round 8
// speedup vs baseline: 5.0702x; 1.0171x over previous
#include <cuda_runtime.h>
#include <cuda_fp16.h>
#include <math.h>
#include <stdint.h>

#define TT   2048
#define DD   1024
#define EE   16
#define HH   1024
#define KK   4
#define TKS  (TT*KK)
#define NWE  (DD*HH)
#define EPSF 1e-6f

// ---------------- device scratch (static; no cudaMalloc) --------------------
__device__ float  g_ssum[EE];
__device__ int    g_counts[EE];
__device__ int    g_offsets[EE];
__device__ int    g_fill[EE];
__device__ int    g_tok[TKS];
__device__ int    g_slot[TKS];
__device__ int    g_topk_e[TKS];
__device__ float  g_topk_w[TKS];
__device__ __half g_xh [(size_t)TT * DD];
__device__ __half g_w1t[(size_t)EE * NWE];      // w1^T per expert: [H][D] fp16
__device__ __half g_w3t[(size_t)EE * NWE];
__device__ __half g_w2t[(size_t)EE * NWE];      // w2^T: [D][H]
__device__ __half g_abuf[(size_t)TKS * HH];
__device__ float  g_ybuf[(size_t)TKS * DD];

// ---------------- helpers ------------------------------------------------------
#define MMA_F16(c, a, b0, b1) \
  asm volatile("mma.sync.aligned.m16n8k16.row.col.f32.f16.f16.f32 " \
    "{%0,%1,%2,%3}, {%4,%5,%6,%7}, {%8,%9}, {%0,%1,%2,%3};" \
    : "+f"((c)[0]), "+f"((c)[1]), "+f"((c)[2]), "+f"((c)[3]) \
    : "r"((a)[0]), "r"((a)[1]), "r"((a)[2]), "r"((a)[3]), "r"(b0), "r"(b1))

__device__ __forceinline__ float silu_mul(float h, float g) {
    return (h / (1.0f + expf(-h))) * g;
}
__device__ __forceinline__ uint32_t smem_u32(const void* p) {
    uint32_t r;
    asm("{ .reg .u64 t; cvta.to.shared.u64 t, %1; cvt.u32.u64 %0, t; }" : "=r"(r) : "l"(p));
    return r;
}
__device__ __forceinline__ void cp16(uint32_t d, const void* s) {
    asm volatile("cp.async.cg.shared.global [%0], [%1], 16;" :: "r"(d), "l"(s));
}
__device__ __forceinline__ void cp_commit() { asm volatile("cp.async.commit_group;" ::: "memory"); }
template<int N>
__device__ __forceinline__ void cp_wait() { asm volatile("cp.async.wait_group %0;" :: "n"(N) : "memory"); }

// SMEM layouts in HALVES, pitch 40 (conflict-free fragments).
#define H13_A(s,m)   ((s)*10240 + (m)*40)
#define H13_B1(s,n)  ((s)*10240 + 5120 + (n)*40)
#define H13_B3(s,n)  ((s)*10240 + 7680 + (n)*40)
#define SMEM13 (3 * 20480)
#define H2_A(s,m)    ((s)*10240 + (m)*40)
#define H2_B(s,n)    ((s)*10240 + 5120 + (n)*40)
#define SMEM2  (3 * 20480)

// ---------------- transpose+convert, 64-row tiles (128B half2 stores) -----------
// src [R=1024][C=1024] fp32 -> dst [C][R] fp16
__device__ __forceinline__ void tcvt_tile(const float* src, __half* dst,
                                          int c0, int r0, int tx, int ty) {
    __shared__ float t[64][33];
    #pragma unroll
    for (int u = 0; u < 8; u++)
        t[ty + 8 * u][tx] = src[(size_t)(r0 + ty + 8 * u) * 1024 + c0 + tx];
    __syncthreads();
    #pragma unroll
    for (int v = 0; v < 4; v++) {
        int j = ty + 8 * v;
        __half2 h = __floats2half2_rn(t[2 * tx][j], t[2 * tx + 1][j]);
        *(__half2*)(dst + (size_t)(c0 + j) * 1024 + r0 + 2 * tx) = h;
    }
}

__global__ void tcvt13_kernel(const float* __restrict__ w1, const float* __restrict__ w3) {
    int which = blockIdx.z >> 4, e = blockIdx.z & 15;
    const float* src = (which ? w3 : w1) + (size_t)e * NWE;
    __half*      dst = (which ? g_w3t : g_w1t) + (size_t)e * NWE;
    tcvt_tile(src, dst, blockIdx.x * 32, blockIdx.y * 64, threadIdx.x, threadIdx.y);
}
__global__ void tcvt2_kernel(const float* __restrict__ w2) {
    int e = blockIdx.z;
    tcvt_tile(w2 + (size_t)e * NWE, g_w2t + (size_t)e * NWE,
              blockIdx.x * 32, blockIdx.y * 64, threadIdx.x, threadIdx.y);
}

// ---------------- router: block-staged gate_w, warp-per-token, fused x->fp16 ----
__global__ void router_kernel(const float* __restrict__ x,
                              const float* __restrict__ gw,
                              const float* __restrict__ bias) {
    extern __shared__ float gws[];             // [EE][DD] transposed, 64KB
    __shared__ float bssum[EE];
    int tid = threadIdx.x;
    if (tid < EE) bssum[tid] = 0.0f;
    for (int i = tid; i < DD * EE; i += 256) {
        int d = i >> 4, e = i & 15;
        gws[e * DD + d] = gw[i];
    }
    __syncthreads();

    int warp = tid >> 5, lane = tid & 31;
    #pragma unroll
    for (int tt = 0; tt < 2; tt++) {
        int t = blockIdx.x * 16 + warp * 2 + tt;
        float acc[EE];
        #pragma unroll
        for (int e = 0; e < EE; e++) acc[e] = 0.0f;
        for (int i = 0; i < DD / 32; i++) {
            int d = i * 32 + lane;
            float xv = x[(size_t)t * DD + d];
            g_xh[(size_t)t * DD + d] = __float2half_rn(xv);
            #pragma unroll
            for (int e = 0; e < EE; e++) acc[e] += xv * gws[e * DD + d];
        }
        #pragma unroll
        for (int o = 16; o; o >>= 1) {
            #pragma unroll
            for (int e = 0; e < EE; e++)
                acc[e] += __shfl_xor_sync(0xffffffff, acc[e], o);
        }
        if (lane == 0) {
            float sc[EE];
            float ssum = 0.0f;
            #pragma unroll
            for (int e = 0; e < EE; e++) {
                sc[e] = 1.0f / (1.0f + expf(-(acc[e] + bias[e])));
                ssum += sc[e];
            }
            float inv = 1.0f / (ssum + EPSF);
            #pragma unroll
            for (int e = 0; e < EE; e++) {
                sc[e] *= inv;
                atomicAdd(&bssum[e], sc[e]);
            }
            unsigned used = 0u;
            int idx[KK]; float val[KK]; float wsum = 0.0f;
            #pragma unroll
            for (int k = 0; k < KK; k++) {
                float best = -1e30f; int bi = 0;
                #pragma unroll
                for (int e = 0; e < EE; e++)
                    if (!((used >> e) & 1u) && sc[e] > best) { best = sc[e]; bi = e; }
                used |= (1u << bi);
                idx[k] = bi; val[k] = best; wsum += best;
            }
            float winv = 1.0f / (wsum + EPSF);
            #pragma unroll
            for (int k = 0; k < KK; k++) {
                g_topk_e[t * KK + k] = idx[k];
                g_topk_w[t * KK + k] = val[k] * winv;
                atomicAdd(&g_counts[idx[k]], 1);
            }
        }
    }
    __syncthreads();
    if (tid < EE) atomicAdd(&g_ssum[tid], bssum[tid]);
}

// ---------------- scan + lb + scatter (single block) ------------------------------
__global__ void scanscatter_kernel(float* __restrict__ out, int out_size) {
    int tid = threadIdx.x;
    if (tid == 0) {
        int off = 0;
        float lb = 0.0f;
        #pragma unroll
        for (int e = 0; e < EE; e++) {
            g_offsets[e] = off;
            off += g_counts[e];
            lb  += (float)g_counts[e] * g_ssum[e];
        }
        lb *= (float)EE / ((float)TT * (float)TT);
        if (out_size > TT * DD) out[TT * DD] = lb;
    }
    // zero any poison beyond the lb slot
    for (int i = TT * DD + 1 + tid; i < out_size; i += 512) out[i] = 0.0f;
    __syncthreads();
    for (int i = tid; i < TKS; i += 512) {
        int t = i >> 2;
        int e = g_topk_e[i];
        int pos = atomicAdd(&g_fill[e], 1);
        int slot = g_offsets[e] + pos;
        g_tok[slot] = t;
        g_slot[i]   = slot;
    }
}

// ---------------- gemm13 fill ------------------------------------------------------
__device__ __forceinline__ void fill13(uint32_t sbase, int st, int c, int tid,
                                       const int* rowb, const __half* w1e,
                                       const __half* w3e, int n0) {
    int k0 = c * 32;
    #pragma unroll
    for (int f = 0; f < 2; f++) {
        int id = tid + 256 * f;
        int m = id >> 2, q = (id & 3) * 8;
        cp16(sbase + (H13_A(st, m) + q) * 2, g_xh + rowb[m] + k0 + q);
    }
    {
        int n = tid >> 2, q = (tid & 3) * 8;
        size_t gofs = (size_t)(n0 + n) * DD + k0 + q;
        cp16(sbase + (H13_B1(st, n) + q) * 2, w1e + gofs);
        cp16(sbase + (H13_B3(st, n) + q) * 2, w3e + gofs);
    }
}

// ---------------- GEMM13: abuf = silu(gather(x)@W1) * (gather(x)@W3) ---------------
__global__ __launch_bounds__(256, 2)
void gemm13_tc() {
    int e   = blockIdx.z;
    int cnt = g_counts[e];
    int m0  = blockIdx.y * 128;
    if (m0 >= cnt) return;
    int off = g_offsets[e];
    int n0  = blockIdx.x * 64;
    const __half* w1e = g_w1t + (size_t)e * NWE;
    const __half* w3e = g_w3t + (size_t)e * NWE;

    extern __shared__ __half sh[];
    uint32_t* smu = (uint32_t*)sh;
    uint32_t sbase = smem_u32(sh);
    __shared__ int rowb[128];

    int tid = threadIdx.x;
    if (tid < 128) {
        int m = m0 + tid;
        rowb[tid] = g_tok[off + (m < cnt ? m : cnt - 1)] * DD;
    }
    __syncthreads();

    int wid = tid >> 5, lane = tid & 31;
    int grp = lane >> 2, tig = lane & 3;
    int wm = wid & 3, wn = wid >> 2;

    float accH[2][4][4], accG[2][4][4];
    #pragma unroll
    for (int i = 0; i < 2; i++)
        #pragma unroll
        for (int j = 0; j < 4; j++)
            #pragma unroll
            for (int q = 0; q < 4; q++) { accH[i][j][q] = 0.0f; accG[i][j][q] = 0.0f; }

    fill13(sbase, 0, 0, tid, rowb, w1e, w3e, n0); cp_commit();
    fill13(sbase, 1, 1, tid, rowb, w1e, w3e, n0); cp_commit();

    for (int c = 0; c < DD / 32; c++) {
        cp_wait<1>();
        __syncthreads();
        if (c + 2 < DD / 32)
            fill13(sbase, (c + 2) % 3, c + 2, tid, rowb, w1e, w3e, n0);
        cp_commit();

        int sl = c % 3;
        int abase0 = sl * 5120;
        int bbase1 = sl * 5120 + 2560;
        int bbase3 = sl * 5120 + 3840;
        #pragma unroll
        for (int s = 0; s < 2; s++) {
            uint32_t afr[2][4];
            #pragma unroll
            for (int i = 0; i < 2; i++) {
                int base = abase0 + (wm * 32 + i * 16 + grp) * 20 + s * 8 + tig;
                afr[i][0] = smu[base];
                afr[i][1] = smu[base + 160];
                afr[i][2] = smu[base + 4];
                afr[i][3] = smu[base + 164];
            }
            #pragma unroll
            for (int j = 0; j < 4; j++) {
                int nw = (wn * 32 + j * 8 + grp) * 20 + s * 8 + tig;
                uint32_t b10 = smu[bbase1 + nw], b11 = smu[bbase1 + nw + 4];
                MMA_F16(accH[0][j], afr[0], b10, b11);
                MMA_F16(accH[1][j], afr[1], b10, b11);
                uint32_t b30 = smu[bbase3 + nw], b31 = smu[bbase3 + nw + 4];
                MMA_F16(accG[0][j], afr[0], b30, b31);
                MMA_F16(accG[1][j], afr[1], b30, b31);
            }
        }
    }

    #pragma unroll
    for (int i = 0; i < 2; i++) {
        int r0 = m0 + wm * 32 + i * 16 + grp;
        #pragma unroll
        for (int j = 0; j < 4; j++) {
            int cb = n0 + wn * 32 + j * 8 + tig * 2;
            if (r0 < cnt) {
                *(__half2*)(g_abuf + (size_t)(off + r0) * HH + cb) =
                    __floats2half2_rn(silu_mul(accH[i][j][0], accG[i][j][0]),
                                      silu_mul(accH[i][j][1], accG[i][j][1]));
            }
            if (r0 + 8 < cnt) {
                *(__half2*)(g_abuf + (size_t)(off + r0 + 8) * HH + cb) =
                    __floats2half2_rn(silu_mul(accH[i][j][2], accG[i][j][2]),
                                      silu_mul(accH[i][j][3], accG[i][j][3]));
            }
        }
    }
}

// ---------------- gemm2 fill (N tile = 128) ----------------------------------------
__device__ __forceinline__ void fill2(uint32_t sbase, int st, int c, int tid,
                                      int arow0, const __half* wB, int n0) {
    int k0 = c * 32;
    #pragma unroll
    for (int f = 0; f < 2; f++) {
        int id = tid + 256 * f;
        int m = id >> 2, q = (id & 3) * 8;
        cp16(sbase + (H2_A(st, m) + q) * 2, g_abuf + (size_t)(arow0 + m) * HH + k0 + q);
    }
    #pragma unroll
    for (int f = 0; f < 2; f++) {
        int id = tid + 256 * f;
        int n = id >> 2, q = (id & 3) * 8;
        cp16(sbase + (H2_B(st, n) + q) * 2, wB + (size_t)(n0 + n) * HH + k0 + q);
    }
}

// ---------------- GEMM2: ybuf = abuf @ W2  (CTA 128x128, warp 64x32) ----------------
__global__ __launch_bounds__(256, 2)
void gemm2_tc() {
    int e   = blockIdx.z;
    int cnt = g_counts[e];
    int m0  = blockIdx.y * 128;
    if (m0 >= cnt) return;
    int off = g_offsets[e];
    int n0  = blockIdx.x * 128;
    const __half* wB = g_w2t + (size_t)e * NWE;

    int arow0 = off + m0;
    if (arow0 > TKS - 128) arow0 = TKS - 128;

    extern __shared__ __half sh[];
    uint32_t* smu = (uint32_t*)sh;
    uint32_t sbase = smem_u32(sh);

    int tid = threadIdx.x;
    int wid = tid >> 5, lane = tid & 31;
    int grp = lane >> 2, tig = lane & 3;
    int wm = wid & 1, wn = wid >> 1;

    float acc[4][4][4];
    #pragma unroll
    for (int i = 0; i < 4; i++)
        #pragma unroll
        for (int j = 0; j < 4; j++)
            #pragma unroll
            for (int q = 0; q < 4; q++) acc[i][j][q] = 0.0f;

    fill2(sbase, 0, 0, tid, arow0, wB, n0); cp_commit();
    fill2(sbase, 1, 1, tid, arow0, wB, n0); cp_commit();

    for (int c = 0; c < HH / 32; c++) {
        cp_wait<1>();
        __syncthreads();
        if (c + 2 < HH / 32)
            fill2(sbase, (c + 2) % 3, c + 2, tid, arow0, wB, n0);
        cp_commit();

        int sl = c % 3;
        int abase0 = sl * 5120;
        int bbase  = sl * 5120 + 2560;
        #pragma unroll
        for (int s = 0; s < 2; s++) {
            uint32_t afr[4][4];
            #pragma unroll
            for (int i = 0; i < 4; i++) {
                int base = abase0 + (wm * 64 + i * 16 + grp) * 20 + s * 8 + tig;
                afr[i][0] = smu[base];
                afr[i][1] = smu[base + 160];
                afr[i][2] = smu[base + 4];
                afr[i][3] = smu[base + 164];
            }
            #pragma unroll
            for (int j = 0; j < 4; j++) {
                int nw = (wn * 32 + j * 8 + grp) * 20 + s * 8 + tig;
                uint32_t b0 = smu[bbase + nw], b1 = smu[bbase + nw + 4];
                #pragma unroll
                for (int i = 0; i < 4; i++)
                    MMA_F16(acc[i][j], afr[i], b0, b1);
            }
        }
    }

    int adj = (off + m0) - arow0;
    #pragma unroll
    for (int i = 0; i < 4; i++) {
        int rr = wm * 64 + i * 16 + grp - adj;
        int r0 = m0 + rr;
        #pragma unroll
        for (int j = 0; j < 4; j++) {
            int cb = n0 + wn * 32 + j * 8 + tig * 2;
            if (rr >= 0 && r0 < cnt)
                *(float2*)(g_ybuf + (size_t)(off + r0) * DD + cb) = make_float2(acc[i][j][0], acc[i][j][1]);
            if (rr + 8 >= 0 && r0 + 8 < cnt)
                *(float2*)(g_ybuf + (size_t)(off + r0 + 8) * DD + cb) = make_float2(acc[i][j][2], acc[i][j][3]);
        }
    }
}

// ---------------- combine (+ counter reset for next call) -------------------------
__global__ void combine_kernel(float* __restrict__ out) {
    int id = blockIdx.x * blockDim.x + threadIdx.x;
    int t  = id >> 8;
    int d4 = (id & 255) * 4;
    float4 acc = make_float4(0.f, 0.f, 0.f, 0.f);
    #pragma unroll
    for (int k = 0; k < KK; k++) {
        int   slot = g_slot[t * KK + k];
        float w    = g_topk_w[t * KK + k];
        float4 v = *(const float4*)(g_ybuf + (size_t)slot * DD + d4);
        acc.x += w * v.x; acc.y += w * v.y; acc.z += w * v.z; acc.w += w * v.w;
    }
    *(float4*)(out + (size_t)t * DD + d4) = acc;
    if (blockIdx.x == 0 && threadIdx.x < EE) {
        g_counts[threadIdx.x] = 0;
        g_ssum[threadIdx.x]   = 0.0f;
        g_fill[threadIdx.x]   = 0;
    }
}

// ---------------- launch ---------------------------------------------------------
extern "C" void kernel_launch(void* const* d_in, const int* in_sizes, int n_in,
                              void* d_out, int out_size) {
    const float* x    = (const float*)d_in[0];
    const float* gw   = (const float*)d_in[1];
    const float* bias = (const float*)d_in[2];
    const float* w1   = (const float*)d_in[3];
    const float* w3   = (const float*)d_in[4];
    const float* w2   = (const float*)d_in[5];
    float* out = (float*)d_out;

    static bool s_init = false;
    static cudaStream_t s2;
    static cudaEvent_t evFork, ev13, ev2;
    if (!s_init) {
        cudaStreamCreateWithFlags(&s2, cudaStreamNonBlocking);
        cudaEventCreateWithFlags(&evFork, cudaEventDisableTiming);
        cudaEventCreateWithFlags(&ev13,   cudaEventDisableTiming);
        cudaEventCreateWithFlags(&ev2,    cudaEventDisableTiming);
        cudaFuncSetAttribute(gemm13_tc, cudaFuncAttributeMaxDynamicSharedMemorySize, SMEM13);
        cudaFuncSetAttribute(gemm2_tc,  cudaFuncAttributeMaxDynamicSharedMemorySize, SMEM2);
        cudaFuncSetAttribute(router_kernel, cudaFuncAttributeMaxDynamicSharedMemorySize, DD * EE * 4);
        s_init = true;
    }

    // fork: weight conversion on s2, routing chain on main stream
    cudaEventRecord(evFork, 0);
    cudaStreamWaitEvent(s2, evFork, 0);
    tcvt13_kernel<<<dim3(32, 16, 32), dim3(32, 8), 0, s2>>>(w1, w3);
    cudaEventRecord(ev13, s2);
    tcvt2_kernel<<<dim3(32, 16, 16), dim3(32, 8), 0, s2>>>(w2);
    cudaEventRecord(ev2, s2);

    router_kernel<<<128, 256, DD * EE * 4>>>(x, gw, bias);
    scanscatter_kernel<<<1, 512>>>(out, out_size);

    cudaStreamWaitEvent(0, ev13, 0);                 // join: w1t/w3t ready
    dim3 g1(HH / 64, TT / 128, EE);
    gemm13_tc<<<g1, 256, SMEM13>>>();

    cudaStreamWaitEvent(0, ev2, 0);                  // join: w2t ready
    dim3 g2(DD / 128, TT / 128, EE);
    gemm2_tc<<<g2, 256, SMEM2>>>();

    combine_kernel<<<(TT * DD / 4) / 256, 256>>>(out);
}